// round 15
// baseline (speedup 1.0000x reference)
#include <cuda_runtime.h>
#include <cuda_fp16.h>
#include <cstdint>
#include <math.h>

#define TT   24
#define BB   64
#define NI   32
#define IL   24
#define VEC  24
#define NS   256
#define HH   256
#define DIN  288
#define LAM  0.2f
#define NTHREADS 1024
#define KC   36
#define JJ   384
#define OHALF 12
#define NCACHE 20      // kc-chunks cached: kc 0..9 and 18..27

typedef unsigned long long ull;

__device__ uint4 g_W4c[2 * KC * JJ];
__device__ float g_gbiasC[2 * JJ];

#define NBAR(id, cnt) asm volatile("bar.sync %0, %1;" :: "r"(id), "r"(cnt) : "memory")

__device__ __forceinline__ float frcp(float x) {
    float y; asm("rcp.approx.f32 %0, %1;" : "=f"(y) : "f"(x)); return y;
}
__device__ __forceinline__ ull pk2(float x, float y) {
    ull r; asm("mov.b64 %0, {%1,%2};" : "=l"(r) : "f"(x), "f"(y)); return r;
}
__device__ __forceinline__ float2 upk(ull v) {
    float2 f; asm("mov.b64 {%0,%1}, %2;" : "=f"(f.x), "=f"(f.y) : "l"(v)); return f;
}
__device__ __forceinline__ ull fma2(ull a, ull b, ull c) {
    ull d; asm("fma.rn.f32x2 %0, %1, %2, %3;" : "=l"(d) : "l"(a), "l"(b), "l"(c)); return d;
}
__device__ __forceinline__ ull mul2(ull a, ull b) {
    ull d; asm("mul.rn.f32x2 %0, %1, %2;" : "=l"(d) : "l"(a), "l"(b)); return d;
}
__device__ __forceinline__ ull rcp2(ull v) {
    float2 f = upk(v); return pk2(frcp(f.x), frcp(f.y));
}
__device__ __forceinline__ unsigned s2u(const void* p) {
    unsigned a; asm("{ .reg .u64 t; cvta.to.shared.u64 t, %1; cvt.u32.u64 %0, t; }" : "=r"(a) : "l"(p)); return a;
}
__device__ __forceinline__ unsigned mapa_u32(unsigned a, unsigned r) {
    unsigned o; asm("mapa.shared::cluster.u32 %0, %1, %2;" : "=r"(o) : "r"(a), "r"(r)); return o;
}
__device__ __forceinline__ void stc_f32(unsigned a, float v) {
    asm volatile("st.shared::cluster.f32 [%0], %1;" :: "r"(a), "f"(v) : "memory");
}
__device__ __forceinline__ void stc_b64(unsigned a, float x, float y) {
    ull u; asm("mov.b64 %0, {%1,%2};" : "=l"(u) : "f"(x), "f"(y));
    asm volatile("st.shared::cluster.b64 [%0], %1;" :: "r"(a), "l"(u) : "memory");
}
__device__ __forceinline__ void mbar_init(unsigned a, unsigned c) {
    asm volatile("mbarrier.init.shared.b64 [%0], %1;" :: "r"(a), "r"(c) : "memory");
}
__device__ __forceinline__ void mbar_arrive_remote(unsigned a) {
    asm volatile("mbarrier.arrive.release.cluster.shared::cluster.b64 _, [%0];" :: "r"(a) : "memory");
}
__device__ __forceinline__ void mbar_wait(unsigned a, unsigned ph) {
    unsigned done;
    asm volatile("{ .reg .pred p; mbarrier.try_wait.parity.acquire.cluster.shared::cta.b64 p, [%1], %2; selp.b32 %0,1,0,p; }"
        : "=r"(done) : "r"(a), "r"(ph) : "memory");
    while (!done) {
        asm volatile("{ .reg .pred p; mbarrier.try_wait.parity.acquire.cluster.shared::cta.b64 p, [%1], %2, 0x989680; selp.b32 %0,1,0,p; }"
            : "=r"(done) : "r"(a), "r"(ph) : "memory");
    }
}
__device__ __forceinline__ unsigned ctarank() {
    unsigned r; asm("mov.u32 %0, %%cluster_ctarank;" : "=r"(r)); return r;
}
__device__ __forceinline__ void cluster_sync_all() {
    asm volatile("barrier.cluster.arrive.aligned;" ::: "memory");
    asm volatile("barrier.cluster.wait.aligned;" ::: "memory");
}

__global__ void prep_kernel(const float* __restrict__ Wih,
                            const float* __restrict__ bih,
                            const float* __restrict__ bhh) {
    int idx = blockIdx.x * blockDim.x + threadIdx.x;
    int total = 2 * KC * JJ;
    for (int i = idx; i < total; i += gridDim.x * blockDim.x) {
        int r  = i / (KC * JJ);
        int rem = i - r * (KC * JJ);
        int kc = rem / JJ, jj = rem - kc * JJ;
        int h = 128 * r + (jj & 127);
        int row = (jj < 128) ? h : (jj < 256) ? (512 + h) : (768 + h);
        const float* src = Wih + row * DIN + kc * 8;
        __half2 h0 = __floats2half2_rn(src[0], src[1]);
        __half2 h1 = __floats2half2_rn(src[2], src[3]);
        __half2 h2 = __floats2half2_rn(src[4], src[5]);
        __half2 h3 = __floats2half2_rn(src[6], src[7]);
        uint4 u;
        u.x = *(unsigned*)&h0; u.y = *(unsigned*)&h1;
        u.z = *(unsigned*)&h2; u.w = *(unsigned*)&h3;
        g_W4c[i] = u;
    }
    if (idx < 2 * JJ) {
        int r = idx / JJ, jj = idx - r * JJ;
        int h = 128 * r + (jj & 127);
        int row = (jj < 128) ? h : (jj < 256) ? (512 + h) : (768 + h);
        g_gbiasC[idx] = bih[row] + bhh[row];
    }
}

// ---------------- smem layout (floats) ----------------
#define SWLL_OFF  0                       // 3072
#define SWLG_OFF  (SWLL_OFF + 3072)       // 3072
#define SINP_OFF  (SWLG_OFF + 3072)       // 6912
#define SGB_OFF   (SINP_OFF + 6912)       // 256
#define GARRL_OFF (SGB_OFF + 256)         // 384
#define GARRG0_OFF (GARRL_OFF + 384)      // 384
#define GARRG1_OFF (GARRG0_OFF + 384)     // 384
#define SBIAS_OFF (GARRG1_OFF + 384)      // 384
#define XV_OFF    (SBIAS_OFF + 384)       // 288 (16B aligned)
#define CVL_OFF   (XV_OFF + 288)          // 128
#define TVLF_OFF  (CVL_OFF + 128)         // 48
#define TVLW_OFF  (TVLF_OFF + 48)         // 48
#define TVGF_OFF  (TVLW_OFF + 48)         // 48
#define TVGW_OFF  (TVGF_OFF + 48)         // 48
#define PSG_OFF   (TVGW_OFF + 48)         // 768
#define PSL_OFF   (PSG_OFF + 768)         // 192 (ypeer overlay)
#define SGP_OFF   (PSL_OFF + 192)         // 256
#define SLP_OFF   (SGP_OFF + 256)         // 32
#define SGV_OFF   (SLP_OFF + 32)          // 256 (raw e_g)
#define ELV_OFF   (SGV_OFF + 256)         // 32  (raw e_l)
#define ISU_OFF   (ELV_OFF + 32)          // 4
#define MBAR_OFF  (ISU_OFF + 4)           // 8 floats = 32B: barE1, barE2g, barP, barE2l
#define WC_OFF    (MBAR_OFF + 8)          // 20*384*4 = 30720
#define SGSB_OFF  (WC_OFF + NCACHE * JJ * 4)
#define SMEM_FLOATS (SGSB_OFF + 8448)
#define SMEM_BYTES  (SMEM_FLOATS * 4)

__global__ __launch_bounds__(NTHREADS, 1) __cluster_dims__(2, 1, 1)
void spatial_attn_kernel(
    const float* __restrict__ local_inputs,
    const float* __restrict__ global_inputs,
    const float* __restrict__ local_states,
    const float* __restrict__ global_states,
    const float* __restrict__ distmat,
    const float* __restrict__ la0,
    const float* __restrict__ ga0,
    const float* __restrict__ Wcl, const float* __restrict__ bcl,
    const float* __restrict__ Wll, const float* __restrict__ bll,
    const float* __restrict__ vl,
    const float* __restrict__ Wcg, const float* __restrict__ bcg,
    const float* __restrict__ Wlg, const float* __restrict__ blg,
    const float* __restrict__ vg,
    float* __restrict__ out)
{
    extern __shared__ float sm[];
    float*  sWll  = sm + SWLL_OFF;
    float*  sWlg  = sm + SWLG_OFF;
    float*  sInp  = sm + SINP_OFF;
    float*  sgb   = sm + SGB_OFF;
    float*  garrL = sm + GARRL_OFF;
    float*  garrG0= sm + GARRG0_OFF;
    float*  garrG1= sm + GARRG1_OFF;
    float*  sbias = sm + SBIAS_OFF;
    float*  xv    = sm + XV_OFF;
    float*  cvl   = sm + CVL_OFF;
    float2* tvlF2 = (float2*)(sm + TVLF_OFF);
    float2* tvlW2 = (float2*)(sm + TVLW_OFF);
    float2* tvgF2 = (float2*)(sm + TVGF_OFF);
    float2* tvgW2 = (float2*)(sm + TVGW_OFF);
    float*  psg   = sm + PSG_OFF;
    float*  psl   = sm + PSL_OFF;
    float*  sgp   = sm + SGP_OFF;
    float*  slp   = sm + SLP_OFF;
    float*  sgv   = sm + SGV_OFF;
    float*  elv   = sm + ELV_OFF;
    float*  isu   = sm + ISU_OFF;
    uint4*  sWcU4 = (uint4*)(sm + WC_OFF);
    float*  sWcg  = sm + WC_OFF;                // overlay: 18432
    float*  sGsA  = sm + WC_OFF + 18432;        // overlay: 8448
    float*  sGsB  = sm + SGSB_OFF;              // 8448
    float*  EgX   = sm + WC_OFF + 26880;        // overlay: 3072
    float*  EgP   = sm + WC_OFF + 18432;        // overlay (after sGsA dead)

    const int b   = blockIdx.x >> 1;
    const unsigned r = ctarank();
    const int tid = threadIdx.x;
    const int w = tid >> 5, lane = tid & 31;
    const ull one2 = 0x3F8000003F800000ULL;

    const unsigned barE1  = s2u(sm + MBAR_OFF);
    const unsigned barE2g = barE1 + 8;
    const unsigned barP   = barE1 + 16;
    const unsigned barE2l = barE1 + 24;
    if (tid == 0) {
        mbar_init(barE1, 24);
        mbar_init(barE2g, 256);
        mbar_init(barP, 512);
        mbar_init(barE2l, 32);
    }
    const unsigned peer = r ^ 1u;
    const unsigned p_ypeer  = mapa_u32(s2u(sm + PSL_OFF), peer);
    const unsigned p_sgp    = mapa_u32(s2u(sm + SGP_OFF), peer);
    const unsigned p_slp    = mapa_u32(s2u(sm + SLP_OFF), peer);
    const unsigned p_EgX    = mapa_u32(s2u(sm + WC_OFF + 26880), peer);
    const unsigned p_barE1  = mapa_u32(barE1, peer);
    const unsigned p_barE2g = mapa_u32(barE2g, peer);
    const unsigned p_barE2l = mapa_u32(barE2l, peer);
    const unsigned p_barP   = mapa_u32(barP, peer);
    float2* ypeer = (float2*)(sm + PSL_OFF);

    __syncthreads();
    cluster_sync_all();

    // ---------- El (local conv): packed o-pairs, threads 768..959 ----------
    ull Elpk = 0;
    if (tid >= 768 && tid < 960) {
        int idx = tid - 768;
        int p = idx >> 5, l = idx & 31;
        int o0 = OHALF * r + 2 * p;
        float acc0 = __ldg(&bcl[o0]), acc1 = __ldg(&bcl[o0 + 1]);
        const float* ls = local_states + b * (NI * IL);
        #pragma unroll
        for (int c = 0; c < IL; c++) {
            float sv = __ldg(&ls[c * NI + l]);
            acc0 = fmaf(__ldg(&Wcl[o0 * IL + c]),       sv, acc0);
            acc1 = fmaf(__ldg(&Wcl[(o0 + 1) * IL + c]), sv, acc1);
        }
        Elpk = pk2(__expf(2.f * acc0), __expf(2.f * acc1));
    }

    // preload persistent + precompute data
    for (int i = tid; i < VEC * IL * NI; i += NTHREADS) sWcg[i] = Wcg[i];
    for (int i = tid; i < TT * DIN; i += NTHREADS) {
        int t = i / DIN, k = i - t * DIN;
        sInp[i] = (k < NI) ? __ldg(&local_inputs[(t * BB + b) * NI + k])
                           : __ldg(&global_inputs[(t * BB + b) * NS + (k - NI)]);
    }
    if (tid < NS) sgb[tid] = LAM * __ldg(&distmat[b * NS + tid]);
    for (int i = tid; i < VEC * 128; i += NTHREADS) {
        int d = i >> 7, hh = i & 127;
        sWll[i] = Wll[d * HH + 128 * r + hh];
        sWlg[i] = Wlg[d * HH + 128 * r + hh];
    }
    if (tid < VEC) {
        float wl = -2.f * __ldg(&vl[tid]);
        float wg = -2.f * (1.f - LAM) * __ldg(&vg[tid]);
        tvlW2[tid] = make_float2(wl, wl);
        tvgW2[tid] = make_float2(wg, wg);
    }
    if (tid < JJ) sbias[tid] = g_gbiasC[r * JJ + tid];
    if (tid < 2) isu[tid] = 1.f;
    __syncthreads();

    // xv for t=0 (attn0 raw, per reference)
    if (tid < NI)        xv[tid] = __ldg(&la0[b * NI + tid]) * sInp[tid];
    else if (tid < DIN)  xv[tid] = __ldg(&ga0[b * NS + (tid - NI)]) * sInp[tid];

    // ---------- Eg precompute: ALL 24 o over this rank's 12-c half ----------
    const int og = tid >> 7;
    const int s0 = tid & 127;
    float a00=0.f,a01=0.f,a10=0.f,a11=0.f,a20=0.f,a21=0.f;
    {
        const float* gsb = global_states + (size_t)b * (NS * NI * IL) + (size_t)(12 * r) * (NS * NI);
        for (int i = tid; i < NS * NI; i += NTHREADS) {
            int s = i >> 5, j = i & 31;
            sGsA[s * 33 + j] = gsb[i];
        }
        __syncthreads();
        for (int ci = 0; ci < 12; ci++) {
            float* cur = (ci & 1) ? sGsB : sGsA;
            float* nxt = (ci & 1) ? sGsA : sGsB;
            if (ci < 11) {
                const float* src = gsb + (size_t)(ci + 1) * (NS * NI);
                for (int i = tid; i < NS * NI; i += NTHREADS) {
                    int s = i >> 5, j = i & 31;
                    nxt[s * 33 + j] = src[i];
                }
            }
            int c = 12 * r + ci;
            #pragma unroll 8
            for (int j = 0; j < NI; j++) {
                float gA = cur[s0 * 33 + j];
                float gB = cur[(s0 + 128) * 33 + j];
                float w0 = sWcg[((og*3+0) * IL + c) * NI + j];
                float w1 = sWcg[((og*3+1) * IL + c) * NI + j];
                float w2 = sWcg[((og*3+2) * IL + c) * NI + j];
                a00 = fmaf(w0, gA, a00); a01 = fmaf(w0, gB, a01);
                a10 = fmaf(w1, gA, a10); a11 = fmaf(w1, gB, a11);
                a20 = fmaf(w2, gA, a20); a21 = fmaf(w2, gB, a21);
            }
            __syncthreads();
        }
    }
    {
        int my_lo = 4 * (int)r;
        if (og < my_lo || og >= my_lo + 4) {
            int base = (og - 4 * (int)peer) * 3;
            stc_f32(p_EgX + (unsigned)(((base+0)*NS + s0      ) * 4), a00);
            stc_f32(p_EgX + (unsigned)(((base+0)*NS + s0 + 128) * 4), a01);
            stc_f32(p_EgX + (unsigned)(((base+1)*NS + s0      ) * 4), a10);
            stc_f32(p_EgX + (unsigned)(((base+1)*NS + s0 + 128) * 4), a11);
            stc_f32(p_EgX + (unsigned)(((base+2)*NS + s0      ) * 4), a20);
            stc_f32(p_EgX + (unsigned)(((base+2)*NS + s0 + 128) * 4), a21);
            mbar_arrive_remote(p_barP);
        } else {
            mbar_wait(barP, 0);
            int base = (og - my_lo) * 3;
            float b0 = __ldg(&bcg[og*3+0]);
            float b1 = __ldg(&bcg[og*3+1]);
            float b2 = __ldg(&bcg[og*3+2]);
            EgP[(base+0)*NS + s0      ] = __expf(2.f * (a00 + EgX[(base+0)*NS + s0      ] + b0));
            EgP[(base+0)*NS + s0 + 128] = __expf(2.f * (a01 + EgX[(base+0)*NS + s0 + 128] + b0));
            EgP[(base+1)*NS + s0      ] = __expf(2.f * (a10 + EgX[(base+1)*NS + s0      ] + b1));
            EgP[(base+1)*NS + s0 + 128] = __expf(2.f * (a11 + EgX[(base+1)*NS + s0 + 128] + b1));
            EgP[(base+2)*NS + s0      ] = __expf(2.f * (a20 + EgX[(base+2)*NS + s0      ] + b2));
            EgP[(base+2)*NS + s0 + 128] = __expf(2.f * (a21 + EgX[(base+2)*NS + s0 + 128] + b2));
        }
    }
    __syncthreads();

    const int grp = tid >> 8;
    const int sdx = tid & 255;
    ull Epk0 = 0, Epk1 = 0;
    if (grp < 3) {
        Epk0 = pk2(EgP[(4*grp + 0) * NS + sdx], EgP[(4*grp + 1) * NS + sdx]);
        Epk1 = pk2(EgP[(4*grp + 2) * NS + sdx], EgP[(4*grp + 3) * NS + sdx]);
    }
    __syncthreads();

    {
        const uint4* src = g_W4c + (size_t)r * (KC * JJ);
        for (int i = tid; i < NCACHE * JJ; i += NTHREADS) {
            int slot = i / JJ, jj = i - slot * JJ;
            int kc = (slot < 10) ? slot : (slot + 8);
            sWcU4[i] = src[kc * JJ + jj];
        }
    }
    __syncthreads();

    float bllreg = 0.f, blgreg = 0.f;
    if (lane == 0 && w < VEC) {
        bllreg = __ldg(&bll[w]);
        blgreg = __ldg(&blg[w]);
    }

    float* out_h  = out;
    float* out_c  = out + TT * BB * HH;
    float* out_la = out_c + BB * HH;
    float* out_ga = out_la + TT * BB * NI;

    cluster_sync_all();

    // Barrier roles per step:
    //   bar1 (896):  {w0-23, w28-31} — garr + isu ready
    //   bar2 (768):  w0-23 — cvl ready
    //   bar3 (960):  w0-29 — tv ready
    //   bar4 (960):  w0-29 — partials ready
    //   barE2g/barE2l: split global/local DSMEM exchanges
    //   __syncthreads(): xv/sgv/elv fan-out + cross-step fence
    for (int t = 0; t < TT; t++) {
        const unsigned ph = (unsigned)(t & 1);

        // ---- gates (w0-23, unnormalized xv, split accumulators) ∥ shadow (w30/31) ----
        if (tid < 2 * JJ) {
            int khalf = tid >= JJ;
            int jj = tid - khalf * JJ;
            const uint4* wg = g_W4c + (size_t)r * (KC * JJ) + jj;
            const uint4* ws = sWcU4 + (khalf * 10) * JJ + jj;
            const float4* xv4 = (const float4*)xv;
            float aG0 = 0.f, aG1 = 0.f;
            #pragma unroll
            for (int q = 10; q < 18; q++) {   // gmem chunks first (MLP), all global-k
                int kc = khalf * 18 + q;
                uint4 ww = wg[(size_t)kc * JJ];
                float4 xa = xv4[2 * kc], xb = xv4[2 * kc + 1];
                float2 f0 = __half22float2(*(__half2*)&ww.x);
                float2 f1 = __half22float2(*(__half2*)&ww.y);
                float2 f2 = __half22float2(*(__half2*)&ww.z);
                float2 f3 = __half22float2(*(__half2*)&ww.w);
                aG0 = fmaf(xa.x, f0.x, aG0); aG1 = fmaf(xa.y, f0.y, aG1);
                aG0 = fmaf(xa.z, f1.x, aG0); aG1 = fmaf(xa.w, f1.y, aG1);
                aG0 = fmaf(xb.x, f2.x, aG0); aG1 = fmaf(xb.y, f2.y, aG1);
                aG0 = fmaf(xb.z, f3.x, aG0); aG1 = fmaf(xb.w, f3.y, aG1);
            }
            if (khalf == 0) {
                float aL0 = 0.f, aL1 = 0.f;
                #pragma unroll
                for (int q = 0; q < 4; q++) {   // kc 0-3 = local inputs
                    uint4 ww = ws[q * JJ];
                    float4 xa = xv4[2 * q], xb = xv4[2 * q + 1];
                    float2 f0 = __half22float2(*(__half2*)&ww.x);
                    float2 f1 = __half22float2(*(__half2*)&ww.y);
                    float2 f2 = __half22float2(*(__half2*)&ww.z);
                    float2 f3 = __half22float2(*(__half2*)&ww.w);
                    aL0 = fmaf(xa.x, f0.x, aL0); aL1 = fmaf(xa.y, f0.y, aL1);
                    aL0 = fmaf(xa.z, f1.x, aL0); aL1 = fmaf(xa.w, f1.y, aL1);
                    aL0 = fmaf(xb.x, f2.x, aL0); aL1 = fmaf(xb.y, f2.y, aL1);
                    aL0 = fmaf(xb.z, f3.x, aL0); aL1 = fmaf(xb.w, f3.y, aL1);
                }
                #pragma unroll
                for (int q = 4; q < 10; q++) {  // kc 4-9 global, cached
                    uint4 ww = ws[q * JJ];
                    float4 xa = xv4[2 * q], xb = xv4[2 * q + 1];
                    float2 f0 = __half22float2(*(__half2*)&ww.x);
                    float2 f1 = __half22float2(*(__half2*)&ww.y);
                    float2 f2 = __half22float2(*(__half2*)&ww.z);
                    float2 f3 = __half22float2(*(__half2*)&ww.w);
                    aG0 = fmaf(xa.x, f0.x, aG0); aG1 = fmaf(xa.y, f0.y, aG1);
                    aG0 = fmaf(xa.z, f1.x, aG0); aG1 = fmaf(xa.w, f1.y, aG1);
                    aG0 = fmaf(xb.x, f2.x, aG0); aG1 = fmaf(xb.y, f2.y, aG1);
                    aG0 = fmaf(xb.z, f3.x, aG0); aG1 = fmaf(xb.w, f3.y, aG1);
                }
                garrL[jj]  = aL0 + aL1;
                garrG0[jj] = aG0 + aG1;
            } else {
                #pragma unroll
                for (int q = 0; q < 10; q++) {  // kc 18-27 global, cached
                    int kc = 18 + q;
                    uint4 ww = ws[q * JJ];
                    float4 xa = xv4[2 * kc], xb = xv4[2 * kc + 1];
                    float2 f0 = __half22float2(*(__half2*)&ww.x);
                    float2 f1 = __half22float2(*(__half2*)&ww.y);
                    float2 f2 = __half22float2(*(__half2*)&ww.z);
                    float2 f3 = __half22float2(*(__half2*)&ww.w);
                    aG0 = fmaf(xa.x, f0.x, aG0); aG1 = fmaf(xa.y, f0.y, aG1);
                    aG0 = fmaf(xa.z, f1.x, aG0); aG1 = fmaf(xa.w, f1.y, aG1);
                    aG0 = fmaf(xb.x, f2.x, aG0); aG1 = fmaf(xb.y, f2.y, aG1);
                    aG0 = fmaf(xb.z, f3.x, aG0); aG1 = fmaf(xb.w, f3.y, aG1);
                }
                garrG1[jj] = aG0 + aG1;
            }
        } else if (w == 30) {
            if (t > 0) {
                float ev[8]; float s = 0.f;
                #pragma unroll
                for (int i = 0; i < 8; i++) { ev[i] = sgv[lane + 32 * i]; s += ev[i]; }
                #pragma unroll
                for (int off = 16; off; off >>= 1) s += __shfl_xor_sync(0xffffffffu, s, off);
                float ig2 = frcp(s);
                if (lane == 0) isu[1] = ig2;
                if (r == 0) {
                    float* og_ = out_ga + (size_t)((t - 1) * BB + b) * NS;
                    #pragma unroll
                    for (int i = 0; i < 8; i++) og_[lane + 32 * i] = ev[i] * ig2;
                }
            }
        } else if (w == 31) {
            if (t > 0) {
                float e = elv[lane];
                float s = e;
                #pragma unroll
                for (int off = 16; off; off >>= 1) s += __shfl_xor_sync(0xffffffffu, s, off);
                float il2 = frcp(s);
                if (lane == 0) isu[0] = il2;
                if (r == 1) out_la[(size_t)((t - 1) * BB + b) * NI + lane] = e * il2;
            }
        }
        if (w < 24 || w >= 28) NBAR(1, 896);

        // ---- LSTM (w0-3) + out_h (w28-31) ----
        if (tid < 128) {
            float isl = isu[0], isg = isu[1];
            float gi = fmaf(garrL[tid], isl,
                       fmaf(garrG0[tid] + garrG1[tid], isg, sbias[tid]));
            float gg = fmaf(garrL[128 + tid], isl,
                       fmaf(garrG0[128 + tid] + garrG1[128 + tid], isg, sbias[128 + tid]));
            float si = frcp(1.f + __expf(-gi));
            float tg = fmaf(-2.f, frcp(1.f + __expf(2.f * gg)), 1.f);
            cvl[tid] = si * tg;
        } else if (tid >= 896) {
            int hid = tid - 896;
            float isl = isu[0], isg = isu[1];
            float gi = fmaf(garrL[hid], isl,
                       fmaf(garrG0[hid] + garrG1[hid], isg, sbias[hid]));
            float gg = fmaf(garrL[128 + hid], isl,
                       fmaf(garrG0[128 + hid] + garrG1[128 + hid], isg, sbias[128 + hid]));
            float go = fmaf(garrL[256 + hid], isl,
                       fmaf(garrG0[256 + hid] + garrG1[256 + hid], isg, sbias[256 + hid]));
            float si = frcp(1.f + __expf(-gi));
            float tg = fmaf(-2.f, frcp(1.f + __expf(2.f * gg)), 1.f);
            float cval = si * tg;
            float so = frcp(1.f + __expf(-go));
            float tc = fmaf(-2.f, frcp(1.f + __expf(2.f * cval)), 1.f);
            int hg = 128 * r + hid;
            out_h[(size_t)(t * BB + b) * HH + hg] = so * tc;
            if (t == TT - 1) out_c[(size_t)b * HH + hg] = cval;
        }
        if (w < 24) NBAR(2, 768);

        // ---- y dots (c-half) + E1 exchange + tv ----
        if (w < VEC) {
            float a = 0.f, bg = 0.f;
            const float* wr  = sWll + w * 128;
            const float* wr2 = sWlg + w * 128;
            #pragma unroll
            for (int i = 0; i < 4; i++) {
                float cc = cvl[lane + 32 * i];
                a  = fmaf(cc, wr[lane + 32 * i], a);
                bg = fmaf(cc, wr2[lane + 32 * i], bg);
            }
            #pragma unroll
            for (int off = 16; off; off >>= 1) {
                a  += __shfl_xor_sync(0xffffffffu, a, off);
                bg += __shfl_xor_sync(0xffffffffu, bg, off);
            }
            if (lane == 0) {
                stc_b64(p_ypeer + (unsigned)(w * 8), a, bg);
                mbar_arrive_remote(p_barE1);
                mbar_wait(barE1, ph);
                float2 p = ypeer[w];
                float Fl = __expf(2.f * (a  + p.x + bllreg));
                float Fg = __expf(2.f * (bg + p.y + blgreg));
                tvlF2[w] = make_float2(Fl, Fl);
                tvgF2[w] = make_float2(Fg, Fg);
            }
        }
        if (w < 30) NBAR(3, 960);

        // ---- partials: packed f32x2 ----
        if (grp < 3) {
            const ull* tF = (const ull*)tvgF2;
            const ull* tW = (const ull*)tvgW2;
            ull acc0 = 0, acc1 = 0;
            #pragma unroll
            for (int dq = 0; dq < 6; dq++) {
                ull F1 = tF[4*dq+0], W1 = tW[4*dq+0];
                ull F2 = tF[4*dq+1], W2 = tW[4*dq+1];
                ull F3 = tF[4*dq+2], W3 = tW[4*dq+2];
                ull F4 = tF[4*dq+3], W4 = tW[4*dq+3];
                {
                    ull D1 = fma2(Epk0, F1, one2), D2 = fma2(Epk0, F2, one2);
                    ull D3 = fma2(Epk0, F3, one2), D4 = fma2(Epk0, F4, one2);
                    ull p12 = mul2(D1, D2), p34 = mul2(D3, D4);
                    ull n12 = fma2(W2, D1, mul2(W1, D2));
                    ull n34 = fma2(W4, D3, mul2(W3, D4));
                    ull num = fma2(n34, p12, mul2(n12, p34));
                    acc0 = fma2(num, rcp2(mul2(p12, p34)), acc0);
                }
                {
                    ull D1 = fma2(Epk1, F1, one2), D2 = fma2(Epk1, F2, one2);
                    ull D3 = fma2(Epk1, F3, one2), D4 = fma2(Epk1, F4, one2);
                    ull p12 = mul2(D1, D2), p34 = mul2(D3, D4);
                    ull n12 = fma2(W2, D1, mul2(W1, D2));
                    ull n34 = fma2(W4, D3, mul2(W3, D4));
                    ull num = fma2(n34, p12, mul2(n12, p34));
                    acc1 = fma2(num, rcp2(mul2(p12, p34)), acc1);
                }
            }
            float2 u0 = upk(acc0), u1 = upk(acc1);
            psg[grp * NS + sdx] = (u0.x + u0.y) + (u1.x + u1.y);
        } else if (tid < 960) {
            int idx = tid - 768;
            const ull* tF = (const ull*)tvlF2;
            const ull* tW = (const ull*)tvlW2;
            ull acc = 0;
            #pragma unroll
            for (int dq = 0; dq < 6; dq++) {
                ull F1 = tF[4*dq+0], W1 = tW[4*dq+0];
                ull F2 = tF[4*dq+1], W2 = tW[4*dq+1];
                ull F3 = tF[4*dq+2], W3 = tW[4*dq+2];
                ull F4 = tF[4*dq+3], W4 = tW[4*dq+3];
                ull D1 = fma2(Elpk, F1, one2), D2 = fma2(Elpk, F2, one2);
                ull D3 = fma2(Elpk, F3, one2), D4 = fma2(Elpk, F4, one2);
                ull p12 = mul2(D1, D2), p34 = mul2(D3, D4);
                ull n12 = fma2(W2, D1, mul2(W1, D2));
                ull n34 = fma2(W4, D3, mul2(W3, D4));
                ull num = fma2(n34, p12, mul2(n12, p34));
                acc = fma2(num, rcp2(mul2(p12, p34)), acc);
            }
            float2 u = upk(acc);
            psl[idx] = u.x + u.y;
        }
        if (w < 30) NBAR(4, 960);

        // ---- split E2 exchanges: global (256) and local (32) decoupled ----
        if (tid < NS) {
            float myg = psg[tid] + psg[NS + tid] + psg[2 * NS + tid];
            float base = myg + sgb[tid];
            stc_f32(p_sgp + (unsigned)(tid * 4), myg);
            mbar_arrive_remote(p_barE2g);
            mbar_wait(barE2g, ph);
            float e = __expf(base + sgp[tid]);
            sgv[tid] = e;
            if (t + 1 < TT) xv[NI + tid] = e * sInp[(t + 1) * DIN + NI + tid];
        } else if (tid < NS + NI) {
            int l = tid - NS;
            float myl = 0.f;
            #pragma unroll
            for (int p = 0; p < 6; p++) myl += psl[p * NI + l];
            stc_f32(p_slp + (unsigned)(l * 4), myl);
            mbar_arrive_remote(p_barE2l);
            mbar_wait(barE2l, ph);
            float e = __expf(myl + slp[l]);
            elv[l] = e;
            if (t + 1 < TT) xv[l] = e * sInp[(t + 1) * DIN + l];
        }
        __syncthreads();
    }

    // epilogue: outputs for t = TT-1
    if (w == 30) {
        float ev[8]; float s = 0.f;
        #pragma unroll
        for (int i = 0; i < 8; i++) { ev[i] = sgv[lane + 32 * i]; s += ev[i]; }
        #pragma unroll
        for (int off = 16; off; off >>= 1) s += __shfl_xor_sync(0xffffffffu, s, off);
        float ig2 = frcp(s);
        if (r == 0) {
            float* og_ = out_ga + (size_t)((TT - 1) * BB + b) * NS;
            #pragma unroll
            for (int i = 0; i < 8; i++) og_[lane + 32 * i] = ev[i] * ig2;
        }
    } else if (w == 31) {
        float e = elv[lane];
        float s = e;
        #pragma unroll
        for (int off = 16; off; off >>= 1) s += __shfl_xor_sync(0xffffffffu, s, off);
        float il2 = frcp(s);
        if (r == 1) out_la[(size_t)((TT - 1) * BB + b) * NI + lane] = e * il2;
    }

    cluster_sync_all();
}

extern "C" void kernel_launch(void* const* d_in, const int* in_sizes, int n_in,
                              void* d_out, int out_size) {
    const float* local_inputs  = (const float*)d_in[0];
    const float* global_inputs = (const float*)d_in[1];
    const float* local_states  = (const float*)d_in[2];
    const float* global_states = (const float*)d_in[3];
    const float* distmat       = (const float*)d_in[4];
    const float* la0           = (const float*)d_in[5];
    const float* ga0           = (const float*)d_in[6];
    const float* Wcl = (const float*)d_in[7];
    const float* bcl = (const float*)d_in[8];
    const float* Wll = (const float*)d_in[9];
    const float* bll = (const float*)d_in[10];
    const float* vl  = (const float*)d_in[11];
    const float* Wcg = (const float*)d_in[12];
    const float* bcg = (const float*)d_in[13];
    const float* Wlg = (const float*)d_in[14];
    const float* blg = (const float*)d_in[15];
    const float* vg  = (const float*)d_in[16];
    const float* Wih = (const float*)d_in[17];
    const float* bih = (const float*)d_in[18];
    const float* bhh = (const float*)d_in[19];
    float* out = (float*)d_out;

    cudaFuncSetAttribute(spatial_attn_kernel,
                         cudaFuncAttributeMaxDynamicSharedMemorySize, SMEM_BYTES);

    prep_kernel<<<(2 * KC * JJ + 255) / 256, 256>>>(Wih, bih, bhh);
    spatial_attn_kernel<<<2 * BB, NTHREADS, SMEM_BYTES>>>(
        local_inputs, global_inputs, local_states, global_states, distmat,
        la0, ga0, Wcl, bcl, Wll, bll, vl, Wcg, bcg, Wlg, blg, vg, out);
}

// round 16
// speedup vs baseline: 1.0126x; 1.0126x over previous
#include <cuda_runtime.h>
#include <cuda_fp16.h>
#include <cstdint>
#include <math.h>

#define TT   24
#define BB   64
#define NI   32
#define IL   24
#define VEC  24
#define NS   256
#define HH   256
#define DIN  288
#define LAM  0.2f
#define NTHREADS 1024
#define KC   36
#define JJ   384
#define OHALF 12
#define NCACHE 20      // kc-chunks cached: kc 0..9 and 18..27

typedef unsigned long long ull;

__device__ uint4 g_W4c[2 * KC * JJ];
__device__ float g_gbiasC[2 * JJ];

#define NBAR(id, cnt) asm volatile("bar.sync %0, %1;" :: "r"(id), "r"(cnt) : "memory")

__device__ __forceinline__ float frcp(float x) {
    float y; asm("rcp.approx.f32 %0, %1;" : "=f"(y) : "f"(x)); return y;
}
__device__ __forceinline__ ull pk2(float x, float y) {
    ull r; asm("mov.b64 %0, {%1,%2};" : "=l"(r) : "f"(x), "f"(y)); return r;
}
__device__ __forceinline__ float2 upk(ull v) {
    float2 f; asm("mov.b64 {%0,%1}, %2;" : "=f"(f.x), "=f"(f.y) : "l"(v)); return f;
}
__device__ __forceinline__ ull fma2(ull a, ull b, ull c) {
    ull d; asm("fma.rn.f32x2 %0, %1, %2, %3;" : "=l"(d) : "l"(a), "l"(b), "l"(c)); return d;
}
__device__ __forceinline__ ull mul2(ull a, ull b) {
    ull d; asm("mul.rn.f32x2 %0, %1, %2;" : "=l"(d) : "l"(a), "l"(b)); return d;
}
__device__ __forceinline__ ull rcp2(ull v) {
    float2 f = upk(v); return pk2(frcp(f.x), frcp(f.y));
}
__device__ __forceinline__ unsigned s2u(const void* p) {
    unsigned a; asm("{ .reg .u64 t; cvta.to.shared.u64 t, %1; cvt.u32.u64 %0, t; }" : "=r"(a) : "l"(p)); return a;
}
__device__ __forceinline__ unsigned mapa_u32(unsigned a, unsigned r) {
    unsigned o; asm("mapa.shared::cluster.u32 %0, %1, %2;" : "=r"(o) : "r"(a), "r"(r)); return o;
}
__device__ __forceinline__ void stc_f32(unsigned a, float v) {
    asm volatile("st.shared::cluster.f32 [%0], %1;" :: "r"(a), "f"(v) : "memory");
}
__device__ __forceinline__ void stc_b64(unsigned a, float x, float y) {
    ull u; asm("mov.b64 %0, {%1,%2};" : "=l"(u) : "f"(x), "f"(y));
    asm volatile("st.shared::cluster.b64 [%0], %1;" :: "r"(a), "l"(u) : "memory");
}
__device__ __forceinline__ void mbar_init(unsigned a, unsigned c) {
    asm volatile("mbarrier.init.shared.b64 [%0], %1;" :: "r"(a), "r"(c) : "memory");
}
__device__ __forceinline__ void mbar_arrive_remote(unsigned a) {
    asm volatile("mbarrier.arrive.release.cluster.shared::cluster.b64 _, [%0];" :: "r"(a) : "memory");
}
__device__ __forceinline__ void mbar_wait(unsigned a, unsigned ph) {
    unsigned done;
    asm volatile("{ .reg .pred p; mbarrier.try_wait.parity.acquire.cluster.shared::cta.b64 p, [%1], %2; selp.b32 %0,1,0,p; }"
        : "=r"(done) : "r"(a), "r"(ph) : "memory");
    while (!done) {
        asm volatile("{ .reg .pred p; mbarrier.try_wait.parity.acquire.cluster.shared::cta.b64 p, [%1], %2, 0x989680; selp.b32 %0,1,0,p; }"
            : "=r"(done) : "r"(a), "r"(ph) : "memory");
    }
}
__device__ __forceinline__ unsigned ctarank() {
    unsigned r; asm("mov.u32 %0, %%cluster_ctarank;" : "=r"(r)); return r;
}
__device__ __forceinline__ void cluster_sync_all() {
    asm volatile("barrier.cluster.arrive.aligned;" ::: "memory");
    asm volatile("barrier.cluster.wait.aligned;" ::: "memory");
}

__global__ void prep_kernel(const float* __restrict__ Wih,
                            const float* __restrict__ bih,
                            const float* __restrict__ bhh) {
    int idx = blockIdx.x * blockDim.x + threadIdx.x;
    int total = 2 * KC * JJ;
    for (int i = idx; i < total; i += gridDim.x * blockDim.x) {
        int r  = i / (KC * JJ);
        int rem = i - r * (KC * JJ);
        int kc = rem / JJ, jj = rem - kc * JJ;
        int h = 128 * r + (jj & 127);
        int row = (jj < 128) ? h : (jj < 256) ? (512 + h) : (768 + h);
        const float* src = Wih + row * DIN + kc * 8;
        __half2 h0 = __floats2half2_rn(src[0], src[1]);
        __half2 h1 = __floats2half2_rn(src[2], src[3]);
        __half2 h2 = __floats2half2_rn(src[4], src[5]);
        __half2 h3 = __floats2half2_rn(src[6], src[7]);
        uint4 u;
        u.x = *(unsigned*)&h0; u.y = *(unsigned*)&h1;
        u.z = *(unsigned*)&h2; u.w = *(unsigned*)&h3;
        g_W4c[i] = u;
    }
    if (idx < 2 * JJ) {
        int r = idx / JJ, jj = idx - r * JJ;
        int h = 128 * r + (jj & 127);
        int row = (jj < 128) ? h : (jj < 256) ? (512 + h) : (768 + h);
        g_gbiasC[idx] = bih[row] + bhh[row];
    }
}

// ---------------- smem layout (floats) ----------------
#define SWLL_OFF  0                       // 3072
#define SWLG_OFF  (SWLL_OFF + 3072)       // 3072
#define SINP_OFF  (SWLG_OFF + 3072)       // 6912
#define SGB_OFF   (SINP_OFF + 6912)       // 256
#define GARRL_OFF (SGB_OFF + 256)         // 384
#define GARRG0_OFF (GARRL_OFF + 384)      // 384
#define GARRG1_OFF (GARRG0_OFF + 384)     // 384
#define SBIAS_OFF (GARRG1_OFF + 384)      // 384
#define XV_OFF    (SBIAS_OFF + 384)       // 288 (16B aligned)
#define CVL_OFF   (XV_OFF + 288)          // 128
#define TVLF_OFF  (CVL_OFF + 128)         // 48
#define TVLW_OFF  (TVLF_OFF + 48)         // 48
#define TVGF_OFF  (TVLW_OFF + 48)         // 48
#define TVGW_OFF  (TVGF_OFF + 48)         // 48
#define PSG_OFF   (TVGW_OFF + 48)         // 768
#define PSL_OFF   (PSG_OFF + 768)         // 192 (ypeer overlay)
#define SGP_OFF   (PSL_OFF + 192)         // 256
#define SLP_OFF   (SGP_OFF + 256)         // 32
#define SGV_OFF   (SLP_OFF + 32)          // 256 (raw e_g)
#define ELV_OFF   (SGV_OFF + 256)         // 32  (raw e_l)
#define ISU_OFF   (ELV_OFF + 32)          // 4
#define MBAR_OFF  (ISU_OFF + 4)           // 8 (3 mbarriers)
#define WC_OFF    (MBAR_OFF + 8)          // 20*384*4 = 30720
#define SGSB_OFF  (WC_OFF + NCACHE * JJ * 4)
#define SMEM_FLOATS (SGSB_OFF + 8448)
#define SMEM_BYTES  (SMEM_FLOATS * 4)

__global__ __launch_bounds__(NTHREADS, 1) __cluster_dims__(2, 1, 1)
void spatial_attn_kernel(
    const float* __restrict__ local_inputs,
    const float* __restrict__ global_inputs,
    const float* __restrict__ local_states,
    const float* __restrict__ global_states,
    const float* __restrict__ distmat,
    const float* __restrict__ la0,
    const float* __restrict__ ga0,
    const float* __restrict__ Wcl, const float* __restrict__ bcl,
    const float* __restrict__ Wll, const float* __restrict__ bll,
    const float* __restrict__ vl,
    const float* __restrict__ Wcg, const float* __restrict__ bcg,
    const float* __restrict__ Wlg, const float* __restrict__ blg,
    const float* __restrict__ vg,
    float* __restrict__ out)
{
    extern __shared__ float sm[];
    float*  sWll  = sm + SWLL_OFF;
    float*  sWlg  = sm + SWLG_OFF;
    float*  sInp  = sm + SINP_OFF;
    float*  sgb   = sm + SGB_OFF;
    float*  garrL = sm + GARRL_OFF;
    float*  garrG0= sm + GARRG0_OFF;
    float*  garrG1= sm + GARRG1_OFF;
    float*  sbias = sm + SBIAS_OFF;
    float*  xv    = sm + XV_OFF;
    float*  cvl   = sm + CVL_OFF;
    float2* tvlF2 = (float2*)(sm + TVLF_OFF);
    float2* tvlW2 = (float2*)(sm + TVLW_OFF);
    float2* tvgF2 = (float2*)(sm + TVGF_OFF);
    float2* tvgW2 = (float2*)(sm + TVGW_OFF);
    float*  psg   = sm + PSG_OFF;
    float*  psl   = sm + PSL_OFF;
    float*  sgp   = sm + SGP_OFF;
    float*  slp   = sm + SLP_OFF;
    float*  sgv   = sm + SGV_OFF;
    float*  elv   = sm + ELV_OFF;
    float*  isu   = sm + ISU_OFF;
    uint4*  sWcU4 = (uint4*)(sm + WC_OFF);
    float*  sWcg  = sm + WC_OFF;                // overlay: 18432
    float*  sGsA  = sm + WC_OFF + 18432;        // overlay: 8448
    float*  sGsB  = sm + SGSB_OFF;              // 8448
    float*  EgX   = sm + WC_OFF + 26880;        // overlay: 3072
    float*  EgP   = sm + WC_OFF + 18432;        // overlay (after sGsA dead)

    const int b   = blockIdx.x >> 1;
    const unsigned r = ctarank();
    const int tid = threadIdx.x;
    const int w = tid >> 5, lane = tid & 31;
    const ull one2 = 0x3F8000003F800000ULL;

    const unsigned barE1 = s2u(sm + MBAR_OFF);
    const unsigned barE2 = barE1 + 8;
    const unsigned barP  = barE1 + 16;
    if (tid == 0) { mbar_init(barE1, 24); mbar_init(barE2, 288); mbar_init(barP, 512); }
    const unsigned peer = r ^ 1u;
    const unsigned p_ypeer = mapa_u32(s2u(sm + PSL_OFF), peer);
    const unsigned p_sgp   = mapa_u32(s2u(sm + SGP_OFF), peer);
    const unsigned p_slp   = mapa_u32(s2u(sm + SLP_OFF), peer);
    const unsigned p_EgX   = mapa_u32(s2u(sm + WC_OFF + 26880), peer);
    const unsigned p_barE1 = mapa_u32(barE1, peer);
    const unsigned p_barE2 = mapa_u32(barE2, peer);
    const unsigned p_barP  = mapa_u32(barP, peer);
    float2* ypeer = (float2*)(sm + PSL_OFF);

    __syncthreads();
    cluster_sync_all();

    // ---------- El (local conv): packed o-pairs, threads 768..959 ----------
    ull Elpk = 0;
    if (tid >= 768 && tid < 960) {
        int idx = tid - 768;
        int p = idx >> 5, l = idx & 31;
        int o0 = OHALF * r + 2 * p;
        float acc0 = __ldg(&bcl[o0]), acc1 = __ldg(&bcl[o0 + 1]);
        const float* ls = local_states + b * (NI * IL);
        #pragma unroll
        for (int c = 0; c < IL; c++) {
            float sv = __ldg(&ls[c * NI + l]);
            acc0 = fmaf(__ldg(&Wcl[o0 * IL + c]),       sv, acc0);
            acc1 = fmaf(__ldg(&Wcl[(o0 + 1) * IL + c]), sv, acc1);
        }
        Elpk = pk2(__expf(2.f * acc0), __expf(2.f * acc1));
    }

    // preload persistent + precompute data
    for (int i = tid; i < VEC * IL * NI; i += NTHREADS) sWcg[i] = Wcg[i];
    for (int i = tid; i < TT * DIN; i += NTHREADS) {
        int t = i / DIN, k = i - t * DIN;
        sInp[i] = (k < NI) ? __ldg(&local_inputs[(t * BB + b) * NI + k])
                           : __ldg(&global_inputs[(t * BB + b) * NS + (k - NI)]);
    }
    if (tid < NS) sgb[tid] = LAM * __ldg(&distmat[b * NS + tid]);
    for (int i = tid; i < VEC * 128; i += NTHREADS) {
        int d = i >> 7, hh = i & 127;
        sWll[i] = Wll[d * HH + 128 * r + hh];
        sWlg[i] = Wlg[d * HH + 128 * r + hh];
    }
    if (tid < VEC) {
        float wl = -2.f * __ldg(&vl[tid]);
        float wg = -2.f * (1.f - LAM) * __ldg(&vg[tid]);
        tvlW2[tid] = make_float2(wl, wl);
        tvgW2[tid] = make_float2(wg, wg);
    }
    if (tid < JJ) sbias[tid] = g_gbiasC[r * JJ + tid];
    if (tid < 2) isu[tid] = 1.f;
    __syncthreads();

    // xv for t=0 (attn0 raw, per reference)
    if (tid < NI)        xv[tid] = __ldg(&la0[b * NI + tid]) * sInp[tid];
    else if (tid < DIN)  xv[tid] = __ldg(&ga0[b * NS + (tid - NI)]) * sInp[tid];

    // ---------- Eg precompute: ALL 24 o over this rank's 12-c half ----------
    const int og = tid >> 7;
    const int s0 = tid & 127;
    float a00=0.f,a01=0.f,a10=0.f,a11=0.f,a20=0.f,a21=0.f;
    {
        const float* gsb = global_states + (size_t)b * (NS * NI * IL) + (size_t)(12 * r) * (NS * NI);
        for (int i = tid; i < NS * NI; i += NTHREADS) {
            int s = i >> 5, j = i & 31;
            sGsA[s * 33 + j] = gsb[i];
        }
        __syncthreads();
        for (int ci = 0; ci < 12; ci++) {
            float* cur = (ci & 1) ? sGsB : sGsA;
            float* nxt = (ci & 1) ? sGsA : sGsB;
            if (ci < 11) {
                const float* src = gsb + (size_t)(ci + 1) * (NS * NI);
                for (int i = tid; i < NS * NI; i += NTHREADS) {
                    int s = i >> 5, j = i & 31;
                    nxt[s * 33 + j] = src[i];
                }
            }
            int c = 12 * r + ci;
            #pragma unroll 8
            for (int j = 0; j < NI; j++) {
                float gA = cur[s0 * 33 + j];
                float gB = cur[(s0 + 128) * 33 + j];
                float w0 = sWcg[((og*3+0) * IL + c) * NI + j];
                float w1 = sWcg[((og*3+1) * IL + c) * NI + j];
                float w2 = sWcg[((og*3+2) * IL + c) * NI + j];
                a00 = fmaf(w0, gA, a00); a01 = fmaf(w0, gB, a01);
                a10 = fmaf(w1, gA, a10); a11 = fmaf(w1, gB, a11);
                a20 = fmaf(w2, gA, a20); a21 = fmaf(w2, gB, a21);
            }
            __syncthreads();
        }
    }
    {
        int my_lo = 4 * (int)r;
        if (og < my_lo || og >= my_lo + 4) {
            int base = (og - 4 * (int)peer) * 3;
            stc_f32(p_EgX + (unsigned)(((base+0)*NS + s0      ) * 4), a00);
            stc_f32(p_EgX + (unsigned)(((base+0)*NS + s0 + 128) * 4), a01);
            stc_f32(p_EgX + (unsigned)(((base+1)*NS + s0      ) * 4), a10);
            stc_f32(p_EgX + (unsigned)(((base+1)*NS + s0 + 128) * 4), a11);
            stc_f32(p_EgX + (unsigned)(((base+2)*NS + s0      ) * 4), a20);
            stc_f32(p_EgX + (unsigned)(((base+2)*NS + s0 + 128) * 4), a21);
            mbar_arrive_remote(p_barP);
        } else {
            mbar_wait(barP, 0);
            int base = (og - my_lo) * 3;
            float b0 = __ldg(&bcg[og*3+0]);
            float b1 = __ldg(&bcg[og*3+1]);
            float b2 = __ldg(&bcg[og*3+2]);
            EgP[(base+0)*NS + s0      ] = __expf(2.f * (a00 + EgX[(base+0)*NS + s0      ] + b0));
            EgP[(base+0)*NS + s0 + 128] = __expf(2.f * (a01 + EgX[(base+0)*NS + s0 + 128] + b0));
            EgP[(base+1)*NS + s0      ] = __expf(2.f * (a10 + EgX[(base+1)*NS + s0      ] + b1));
            EgP[(base+1)*NS + s0 + 128] = __expf(2.f * (a11 + EgX[(base+1)*NS + s0 + 128] + b1));
            EgP[(base+2)*NS + s0      ] = __expf(2.f * (a20 + EgX[(base+2)*NS + s0      ] + b2));
            EgP[(base+2)*NS + s0 + 128] = __expf(2.f * (a21 + EgX[(base+2)*NS + s0 + 128] + b2));
        }
    }
    __syncthreads();

    const int grp = tid >> 8;
    const int sdx = tid & 255;
    ull Epk0 = 0, Epk1 = 0;
    if (grp < 3) {
        Epk0 = pk2(EgP[(4*grp + 0) * NS + sdx], EgP[(4*grp + 1) * NS + sdx]);
        Epk1 = pk2(EgP[(4*grp + 2) * NS + sdx], EgP[(4*grp + 3) * NS + sdx]);
    }
    __syncthreads();

    {
        const uint4* src = g_W4c + (size_t)r * (KC * JJ);
        for (int i = tid; i < NCACHE * JJ; i += NTHREADS) {
            int slot = i / JJ, jj = i - slot * JJ;
            int kc = (slot < 10) ? slot : (slot + 8);
            sWcU4[i] = src[kc * JJ + jj];
        }
    }
    __syncthreads();

    float bllreg = 0.f, blgreg = 0.f;
    if (lane == 0 && w < VEC) {
        bllreg = __ldg(&bll[w]);
        blgreg = __ldg(&blg[w]);
    }

    float* out_h  = out;
    float* out_c  = out + TT * BB * HH;
    float* out_la = out_c + BB * HH;
    float* out_ga = out_la + TT * BB * NI;

    cluster_sync_all();

    // Barrier roles per step:
    //   bar1 (896):  {w0-23, w28-31} — garr + isu ready
    //   bar2 (768):  w0-23 — cvl ready
    //   bar3 (960):  w0-29 — tv ready
    //   bar4 (960):  w0-29 — partials ready
    //   __syncthreads(): xv/sgv/elv fan-out + cross-step fence
    for (int t = 0; t < TT; t++) {
        const unsigned ph = (unsigned)(t & 1);

        // ---- gates (w0-23, unnormalized xv, split accumulators) ∥ shadow (w30/31) ----
        if (tid < 2 * JJ) {
            int khalf = tid >= JJ;
            int jj = tid - khalf * JJ;
            const uint4* wg = g_W4c + (size_t)r * (KC * JJ) + jj;
            const uint4* ws = sWcU4 + (khalf * 10) * JJ + jj;
            const float4* xv4 = (const float4*)xv;
            float aG0 = 0.f, aG1 = 0.f;
            #pragma unroll
            for (int q = 10; q < 18; q++) {   // gmem chunks first (MLP), all global-k
                int kc = khalf * 18 + q;
                uint4 ww = wg[(size_t)kc * JJ];
                float4 xa = xv4[2 * kc], xb = xv4[2 * kc + 1];
                float2 f0 = __half22float2(*(__half2*)&ww.x);
                float2 f1 = __half22float2(*(__half2*)&ww.y);
                float2 f2 = __half22float2(*(__half2*)&ww.z);
                float2 f3 = __half22float2(*(__half2*)&ww.w);
                aG0 = fmaf(xa.x, f0.x, aG0); aG1 = fmaf(xa.y, f0.y, aG1);
                aG0 = fmaf(xa.z, f1.x, aG0); aG1 = fmaf(xa.w, f1.y, aG1);
                aG0 = fmaf(xb.x, f2.x, aG0); aG1 = fmaf(xb.y, f2.y, aG1);
                aG0 = fmaf(xb.z, f3.x, aG0); aG1 = fmaf(xb.w, f3.y, aG1);
            }
            if (khalf == 0) {
                float aL0 = 0.f, aL1 = 0.f;
                #pragma unroll
                for (int q = 0; q < 4; q++) {   // kc 0-3 = local inputs
                    uint4 ww = ws[q * JJ];
                    float4 xa = xv4[2 * q], xb = xv4[2 * q + 1];
                    float2 f0 = __half22float2(*(__half2*)&ww.x);
                    float2 f1 = __half22float2(*(__half2*)&ww.y);
                    float2 f2 = __half22float2(*(__half2*)&ww.z);
                    float2 f3 = __half22float2(*(__half2*)&ww.w);
                    aL0 = fmaf(xa.x, f0.x, aL0); aL1 = fmaf(xa.y, f0.y, aL1);
                    aL0 = fmaf(xa.z, f1.x, aL0); aL1 = fmaf(xa.w, f1.y, aL1);
                    aL0 = fmaf(xb.x, f2.x, aL0); aL1 = fmaf(xb.y, f2.y, aL1);
                    aL0 = fmaf(xb.z, f3.x, aL0); aL1 = fmaf(xb.w, f3.y, aL1);
                }
                #pragma unroll
                for (int q = 4; q < 10; q++) {  // kc 4-9 global, cached
                    uint4 ww = ws[q * JJ];
                    float4 xa = xv4[2 * q], xb = xv4[2 * q + 1];
                    float2 f0 = __half22float2(*(__half2*)&ww.x);
                    float2 f1 = __half22float2(*(__half2*)&ww.y);
                    float2 f2 = __half22float2(*(__half2*)&ww.z);
                    float2 f3 = __half22float2(*(__half2*)&ww.w);
                    aG0 = fmaf(xa.x, f0.x, aG0); aG1 = fmaf(xa.y, f0.y, aG1);
                    aG0 = fmaf(xa.z, f1.x, aG0); aG1 = fmaf(xa.w, f1.y, aG1);
                    aG0 = fmaf(xb.x, f2.x, aG0); aG1 = fmaf(xb.y, f2.y, aG1);
                    aG0 = fmaf(xb.z, f3.x, aG0); aG1 = fmaf(xb.w, f3.y, aG1);
                }
                garrL[jj]  = aL0 + aL1;
                garrG0[jj] = aG0 + aG1;
            } else {
                #pragma unroll
                for (int q = 0; q < 10; q++) {  // kc 18-27 global, cached
                    int kc = 18 + q;
                    uint4 ww = ws[q * JJ];
                    float4 xa = xv4[2 * kc], xb = xv4[2 * kc + 1];
                    float2 f0 = __half22float2(*(__half2*)&ww.x);
                    float2 f1 = __half22float2(*(__half2*)&ww.y);
                    float2 f2 = __half22float2(*(__half2*)&ww.z);
                    float2 f3 = __half22float2(*(__half2*)&ww.w);
                    aG0 = fmaf(xa.x, f0.x, aG0); aG1 = fmaf(xa.y, f0.y, aG1);
                    aG0 = fmaf(xa.z, f1.x, aG0); aG1 = fmaf(xa.w, f1.y, aG1);
                    aG0 = fmaf(xb.x, f2.x, aG0); aG1 = fmaf(xb.y, f2.y, aG1);
                    aG0 = fmaf(xb.z, f3.x, aG0); aG1 = fmaf(xb.w, f3.y, aG1);
                }
                garrG1[jj] = aG0 + aG1;
            }
        } else if (w == 30) {
            if (t > 0) {
                float ev[8]; float s = 0.f;
                #pragma unroll
                for (int i = 0; i < 8; i++) { ev[i] = sgv[lane + 32 * i]; s += ev[i]; }
                #pragma unroll
                for (int off = 16; off; off >>= 1) s += __shfl_xor_sync(0xffffffffu, s, off);
                float ig2 = frcp(s);
                if (lane == 0) isu[1] = ig2;
                if (r == 0) {
                    float* og_ = out_ga + (size_t)((t - 1) * BB + b) * NS;
                    #pragma unroll
                    for (int i = 0; i < 8; i++) og_[lane + 32 * i] = ev[i] * ig2;
                }
            }
        } else if (w == 31) {
            if (t > 0) {
                float e = elv[lane];
                float s = e;
                #pragma unroll
                for (int off = 16; off; off >>= 1) s += __shfl_xor_sync(0xffffffffu, s, off);
                float il2 = frcp(s);
                if (lane == 0) isu[0] = il2;
                if (r == 1) out_la[(size_t)((t - 1) * BB + b) * NI + lane] = e * il2;
            }
        }
        if (w < 24 || w >= 28) NBAR(1, 896);

        // ---- LSTM (w0-3) + out_h (w28-31) ----
        if (tid < 128) {
            float isl = isu[0], isg = isu[1];
            float gi = fmaf(garrL[tid], isl,
                       fmaf(garrG0[tid] + garrG1[tid], isg, sbias[tid]));
            float gg = fmaf(garrL[128 + tid], isl,
                       fmaf(garrG0[128 + tid] + garrG1[128 + tid], isg, sbias[128 + tid]));
            float si = frcp(1.f + __expf(-gi));
            float tg = fmaf(-2.f, frcp(1.f + __expf(2.f * gg)), 1.f);
            cvl[tid] = si * tg;
        } else if (tid >= 896) {
            int hid = tid - 896;
            float isl = isu[0], isg = isu[1];
            float gi = fmaf(garrL[hid], isl,
                       fmaf(garrG0[hid] + garrG1[hid], isg, sbias[hid]));
            float gg = fmaf(garrL[128 + hid], isl,
                       fmaf(garrG0[128 + hid] + garrG1[128 + hid], isg, sbias[128 + hid]));
            float go = fmaf(garrL[256 + hid], isl,
                       fmaf(garrG0[256 + hid] + garrG1[256 + hid], isg, sbias[256 + hid]));
            float si = frcp(1.f + __expf(-gi));
            float tg = fmaf(-2.f, frcp(1.f + __expf(2.f * gg)), 1.f);
            float cval = si * tg;
            float so = frcp(1.f + __expf(-go));
            float tc = fmaf(-2.f, frcp(1.f + __expf(2.f * cval)), 1.f);
            int hg = 128 * r + hid;
            out_h[(size_t)(t * BB + b) * HH + hg] = so * tc;
            if (t == TT - 1) out_c[(size_t)b * HH + hg] = cval;
        }
        if (w < 24) NBAR(2, 768);

        // ---- y dots (c-half) + E1 exchange + tv ----
        if (w < VEC) {
            float a = 0.f, bg = 0.f;
            const float* wr  = sWll + w * 128;
            const float* wr2 = sWlg + w * 128;
            #pragma unroll
            for (int i = 0; i < 4; i++) {
                float cc = cvl[lane + 32 * i];
                a  = fmaf(cc, wr[lane + 32 * i], a);
                bg = fmaf(cc, wr2[lane + 32 * i], bg);
            }
            #pragma unroll
            for (int off = 16; off; off >>= 1) {
                a  += __shfl_xor_sync(0xffffffffu, a, off);
                bg += __shfl_xor_sync(0xffffffffu, bg, off);
            }
            if (lane == 0) {
                stc_b64(p_ypeer + (unsigned)(w * 8), a, bg);
                mbar_arrive_remote(p_barE1);
                mbar_wait(barE1, ph);
                float2 p = ypeer[w];
                float Fl = __expf(2.f * (a  + p.x + bllreg));
                float Fg = __expf(2.f * (bg + p.y + blgreg));
                tvlF2[w] = make_float2(Fl, Fl);
                tvgF2[w] = make_float2(Fg, Fg);
            }
        }
        if (w < 30) NBAR(3, 960);

        // ---- partials: packed f32x2 ----
        if (grp < 3) {
            const ull* tF = (const ull*)tvgF2;
            const ull* tW = (const ull*)tvgW2;
            ull acc0 = 0, acc1 = 0;
            #pragma unroll
            for (int dq = 0; dq < 6; dq++) {
                ull F1 = tF[4*dq+0], W1 = tW[4*dq+0];
                ull F2 = tF[4*dq+1], W2 = tW[4*dq+1];
                ull F3 = tF[4*dq+2], W3 = tW[4*dq+2];
                ull F4 = tF[4*dq+3], W4 = tW[4*dq+3];
                {
                    ull D1 = fma2(Epk0, F1, one2), D2 = fma2(Epk0, F2, one2);
                    ull D3 = fma2(Epk0, F3, one2), D4 = fma2(Epk0, F4, one2);
                    ull p12 = mul2(D1, D2), p34 = mul2(D3, D4);
                    ull n12 = fma2(W2, D1, mul2(W1, D2));
                    ull n34 = fma2(W4, D3, mul2(W3, D4));
                    ull num = fma2(n34, p12, mul2(n12, p34));
                    acc0 = fma2(num, rcp2(mul2(p12, p34)), acc0);
                }
                {
                    ull D1 = fma2(Epk1, F1, one2), D2 = fma2(Epk1, F2, one2);
                    ull D3 = fma2(Epk1, F3, one2), D4 = fma2(Epk1, F4, one2);
                    ull p12 = mul2(D1, D2), p34 = mul2(D3, D4);
                    ull n12 = fma2(W2, D1, mul2(W1, D2));
                    ull n34 = fma2(W4, D3, mul2(W3, D4));
                    ull num = fma2(n34, p12, mul2(n12, p34));
                    acc1 = fma2(num, rcp2(mul2(p12, p34)), acc1);
                }
            }
            float2 u0 = upk(acc0), u1 = upk(acc1);
            psg[grp * NS + sdx] = (u0.x + u0.y) + (u1.x + u1.y);
        } else if (tid < 960) {
            int idx = tid - 768;
            const ull* tF = (const ull*)tvlF2;
            const ull* tW = (const ull*)tvlW2;
            ull acc = 0;
            #pragma unroll
            for (int dq = 0; dq < 6; dq++) {
                ull F1 = tF[4*dq+0], W1 = tW[4*dq+0];
                ull F2 = tF[4*dq+1], W2 = tW[4*dq+1];
                ull F3 = tF[4*dq+2], W3 = tW[4*dq+2];
                ull F4 = tF[4*dq+3], W4 = tW[4*dq+3];
                ull D1 = fma2(Elpk, F1, one2), D2 = fma2(Elpk, F2, one2);
                ull D3 = fma2(Elpk, F3, one2), D4 = fma2(Elpk, F4, one2);
                ull p12 = mul2(D1, D2), p34 = mul2(D3, D4);
                ull n12 = fma2(W2, D1, mul2(W1, D2));
                ull n34 = fma2(W4, D3, mul2(W3, D4));
                ull num = fma2(n34, p12, mul2(n12, p34));
                acc = fma2(num, rcp2(mul2(p12, p34)), acc);
            }
            float2 u = upk(acc);
            psl[idx] = u.x + u.y;
        }
        if (w < 30) NBAR(4, 960);

        // ---- reduce + E2 exchange + raw exp + xv(t+1) ----
        if (tid < NS) {
            float myg = psg[tid] + psg[NS + tid] + psg[2 * NS + tid];
            float base = myg + sgb[tid];          // hide FADD in pre-wait slot
            stc_f32(p_sgp + (unsigned)(tid * 4), myg);
            mbar_arrive_remote(p_barE2);
            mbar_wait(barE2, ph);
            float e = __expf(base + sgp[tid]);
            sgv[tid] = e;
            if (t + 1 < TT) xv[NI + tid] = e * sInp[(t + 1) * DIN + NI + tid];
        } else if (tid < NS + NI) {
            int l = tid - NS;
            float myl = 0.f;
            #pragma unroll
            for (int p = 0; p < 6; p++) myl += psl[p * NI + l];
            stc_f32(p_slp + (unsigned)(l * 4), myl);
            mbar_arrive_remote(p_barE2);
            mbar_wait(barE2, ph);
            float e = __expf(myl + slp[l]);
            elv[l] = e;
            if (t + 1 < TT) xv[l] = e * sInp[(t + 1) * DIN + l];
        }
        __syncthreads();
    }

    // epilogue: outputs for t = TT-1
    if (w == 30) {
        float ev[8]; float s = 0.f;
        #pragma unroll
        for (int i = 0; i < 8; i++) { ev[i] = sgv[lane + 32 * i]; s += ev[i]; }
        #pragma unroll
        for (int off = 16; off; off >>= 1) s += __shfl_xor_sync(0xffffffffu, s, off);
        float ig2 = frcp(s);
        if (r == 0) {
            float* og_ = out_ga + (size_t)((TT - 1) * BB + b) * NS;
            #pragma unroll
            for (int i = 0; i < 8; i++) og_[lane + 32 * i] = ev[i] * ig2;
        }
    } else if (w == 31) {
        float e = elv[lane];
        float s = e;
        #pragma unroll
        for (int off = 16; off; off >>= 1) s += __shfl_xor_sync(0xffffffffu, s, off);
        float il2 = frcp(s);
        if (r == 1) out_la[(size_t)((TT - 1) * BB + b) * NI + lane] = e * il2;
    }

    cluster_sync_all();
}

extern "C" void kernel_launch(void* const* d_in, const int* in_sizes, int n_in,
                              void* d_out, int out_size) {
    const float* local_inputs  = (const float*)d_in[0];
    const float* global_inputs = (const float*)d_in[1];
    const float* local_states  = (const float*)d_in[2];
    const float* global_states = (const float*)d_in[3];
    const float* distmat       = (const float*)d_in[4];
    const float* la0           = (const float*)d_in[5];
    const float* ga0           = (const float*)d_in[6];
    const float* Wcl = (const float*)d_in[7];
    const float* bcl = (const float*)d_in[8];
    const float* Wll = (const float*)d_in[9];
    const float* bll = (const float*)d_in[10];
    const float* vl  = (const float*)d_in[11];
    const float* Wcg = (const float*)d_in[12];
    const float* bcg = (const float*)d_in[13];
    const float* Wlg = (const float*)d_in[14];
    const float* blg = (const float*)d_in[15];
    const float* vg  = (const float*)d_in[16];
    const float* Wih = (const float*)d_in[17];
    const float* bih = (const float*)d_in[18];
    const float* bhh = (const float*)d_in[19];
    float* out = (float*)d_out;

    cudaFuncSetAttribute(spatial_attn_kernel,
                         cudaFuncAttributeMaxDynamicSharedMemorySize, SMEM_BYTES);

    prep_kernel<<<(2 * KC * JJ + 255) / 256, 256>>>(Wih, bih, bhh);
    spatial_attn_kernel<<<2 * BB, NTHREADS, SMEM_BYTES>>>(
        local_inputs, global_inputs, local_states, global_states, distmat,
        la0, ga0, Wcl, bcl, Wll, bll, vl, Wcg, bcg, Wlg, blg, vg, out);
}

// round 17
// speedup vs baseline: 1.0248x; 1.0121x over previous
#include <cuda_runtime.h>
#include <cuda_fp16.h>
#include <cstdint>
#include <math.h>

#define TT   24
#define BB   64
#define NI   32
#define IL   24
#define VEC  24
#define NS   256
#define HH   256
#define DIN  288
#define LAM  0.2f
#define NTHREADS 1024
#define KC   36
#define JJ   384
#define OHALF 12
#define NCACHE 20      // kc-chunks cached: kc 0..9 and 18..27

typedef unsigned long long ull;

__device__ uint4 g_W4c[2 * KC * JJ];
__device__ float g_gbiasC[2 * JJ];

#define NBAR(id, cnt) asm volatile("bar.sync %0, %1;" :: "r"(id), "r"(cnt) : "memory")

__device__ __forceinline__ float frcp(float x) {
    float y; asm("rcp.approx.f32 %0, %1;" : "=f"(y) : "f"(x)); return y;
}
__device__ __forceinline__ ull pk2(float x, float y) {
    ull r; asm("mov.b64 %0, {%1,%2};" : "=l"(r) : "f"(x), "f"(y)); return r;
}
__device__ __forceinline__ float2 upk(ull v) {
    float2 f; asm("mov.b64 {%0,%1}, %2;" : "=f"(f.x), "=f"(f.y) : "l"(v)); return f;
}
__device__ __forceinline__ ull fma2(ull a, ull b, ull c) {
    ull d; asm("fma.rn.f32x2 %0, %1, %2, %3;" : "=l"(d) : "l"(a), "l"(b), "l"(c)); return d;
}
__device__ __forceinline__ ull mul2(ull a, ull b) {
    ull d; asm("mul.rn.f32x2 %0, %1, %2;" : "=l"(d) : "l"(a), "l"(b)); return d;
}
__device__ __forceinline__ ull rcp2(ull v) {
    float2 f = upk(v); return pk2(frcp(f.x), frcp(f.y));
}
__device__ __forceinline__ unsigned s2u(const void* p) {
    unsigned a; asm("{ .reg .u64 t; cvta.to.shared.u64 t, %1; cvt.u32.u64 %0, t; }" : "=r"(a) : "l"(p)); return a;
}
__device__ __forceinline__ unsigned mapa_u32(unsigned a, unsigned r) {
    unsigned o; asm("mapa.shared::cluster.u32 %0, %1, %2;" : "=r"(o) : "r"(a), "r"(r)); return o;
}
__device__ __forceinline__ void stc_f32(unsigned a, float v) {
    asm volatile("st.shared::cluster.f32 [%0], %1;" :: "r"(a), "f"(v) : "memory");
}
__device__ __forceinline__ void stc_b64(unsigned a, float x, float y) {
    ull u; asm("mov.b64 %0, {%1,%2};" : "=l"(u) : "f"(x), "f"(y));
    asm volatile("st.shared::cluster.b64 [%0], %1;" :: "r"(a), "l"(u) : "memory");
}
__device__ __forceinline__ void mbar_init(unsigned a, unsigned c) {
    asm volatile("mbarrier.init.shared.b64 [%0], %1;" :: "r"(a), "r"(c) : "memory");
}
__device__ __forceinline__ void mbar_arrive_remote(unsigned a) {
    asm volatile("mbarrier.arrive.release.cluster.shared::cluster.b64 _, [%0];" :: "r"(a) : "memory");
}
__device__ __forceinline__ void mbar_wait(unsigned a, unsigned ph) {
    unsigned done;
    asm volatile("{ .reg .pred p; mbarrier.try_wait.parity.acquire.cluster.shared::cta.b64 p, [%1], %2; selp.b32 %0,1,0,p; }"
        : "=r"(done) : "r"(a), "r"(ph) : "memory");
    while (!done) {
        asm volatile("{ .reg .pred p; mbarrier.try_wait.parity.acquire.cluster.shared::cta.b64 p, [%1], %2, 0x989680; selp.b32 %0,1,0,p; }"
            : "=r"(done) : "r"(a), "r"(ph) : "memory");
    }
}
__device__ __forceinline__ unsigned ctarank() {
    unsigned r; asm("mov.u32 %0, %%cluster_ctarank;" : "=r"(r)); return r;
}
__device__ __forceinline__ void cluster_sync_all() {
    asm volatile("barrier.cluster.arrive.aligned;" ::: "memory");
    asm volatile("barrier.cluster.wait.aligned;" ::: "memory");
}

__global__ void prep_kernel(const float* __restrict__ Wih,
                            const float* __restrict__ bih,
                            const float* __restrict__ bhh) {
    int idx = blockIdx.x * blockDim.x + threadIdx.x;
    int total = 2 * KC * JJ;
    for (int i = idx; i < total; i += gridDim.x * blockDim.x) {
        int r  = i / (KC * JJ);
        int rem = i - r * (KC * JJ);
        int kc = rem / JJ, jj = rem - kc * JJ;
        int h = 128 * r + (jj & 127);
        int row = (jj < 128) ? h : (jj < 256) ? (512 + h) : (768 + h);
        const float* src = Wih + row * DIN + kc * 8;
        __half2 h0 = __floats2half2_rn(src[0], src[1]);
        __half2 h1 = __floats2half2_rn(src[2], src[3]);
        __half2 h2 = __floats2half2_rn(src[4], src[5]);
        __half2 h3 = __floats2half2_rn(src[6], src[7]);
        uint4 u;
        u.x = *(unsigned*)&h0; u.y = *(unsigned*)&h1;
        u.z = *(unsigned*)&h2; u.w = *(unsigned*)&h3;
        g_W4c[i] = u;
    }
    if (idx < 2 * JJ) {
        int r = idx / JJ, jj = idx - r * JJ;
        int h = 128 * r + (jj & 127);
        int row = (jj < 128) ? h : (jj < 256) ? (512 + h) : (768 + h);
        g_gbiasC[idx] = bih[row] + bhh[row];
    }
}

// ---------------- smem layout (floats) ----------------
#define SWLL_OFF  0                       // 3072
#define SWLG_OFF  (SWLL_OFF + 3072)       // 3072
#define SINP_OFF  (SWLG_OFF + 3072)       // 6912
#define SGB_OFF   (SINP_OFF + 6912)       // 256
#define GARRL_OFF (SGB_OFF + 256)         // 384
#define GARRG0_OFF (GARRL_OFF + 384)      // 384
#define GARRG1_OFF (GARRG0_OFF + 384)     // 384
#define SBIAS_OFF (GARRG1_OFF + 384)      // 384
#define XV_OFF    (SBIAS_OFF + 384)       // 288 (16B aligned)
#define CVL_OFF   (XV_OFF + 288)          // 128
#define TVLF_OFF  (CVL_OFF + 128)         // 48
#define TVLW_OFF  (TVLF_OFF + 48)         // 48
#define TVGF_OFF  (TVLW_OFF + 48)         // 48
#define TVGW_OFF  (TVGF_OFF + 48)         // 48
#define PSG_OFF   (TVGW_OFF + 48)         // 768
#define PSL_OFF   (PSG_OFF + 768)         // 192 (ypeer overlay)
#define SGP_OFF   (PSL_OFF + 192)         // 256
#define SLP_OFF   (SGP_OFF + 256)         // 32
#define SGV_OFF   (SLP_OFF + 32)          // 256 (raw e_g)
#define ELV_OFF   (SGV_OFF + 256)         // 32  (raw e_l)
#define ISU_OFF   (ELV_OFF + 32)          // 4
#define MBAR_OFF  (ISU_OFF + 4)           // 8 (3 mbarriers)
#define WC_OFF    (MBAR_OFF + 8)          // 20*384*4 = 30720
#define SGSB_OFF  (WC_OFF + NCACHE * JJ * 4)
#define SMEM_FLOATS (SGSB_OFF + 8448)
#define SMEM_BYTES  (SMEM_FLOATS * 4)

__global__ __launch_bounds__(NTHREADS, 1) __cluster_dims__(2, 1, 1)
void spatial_attn_kernel(
    const float* __restrict__ local_inputs,
    const float* __restrict__ global_inputs,
    const float* __restrict__ local_states,
    const float* __restrict__ global_states,
    const float* __restrict__ distmat,
    const float* __restrict__ la0,
    const float* __restrict__ ga0,
    const float* __restrict__ Wcl, const float* __restrict__ bcl,
    const float* __restrict__ Wll, const float* __restrict__ bll,
    const float* __restrict__ vl,
    const float* __restrict__ Wcg, const float* __restrict__ bcg,
    const float* __restrict__ Wlg, const float* __restrict__ blg,
    const float* __restrict__ vg,
    float* __restrict__ out)
{
    extern __shared__ float sm[];
    float*  sWll  = sm + SWLL_OFF;
    float*  sWlg  = sm + SWLG_OFF;
    float*  sInp  = sm + SINP_OFF;
    float*  sgb   = sm + SGB_OFF;
    float*  garrL = sm + GARRL_OFF;
    float*  garrG0= sm + GARRG0_OFF;
    float*  garrG1= sm + GARRG1_OFF;
    float*  sbias = sm + SBIAS_OFF;
    float*  xv    = sm + XV_OFF;
    float*  cvl   = sm + CVL_OFF;
    float2* tvlF2 = (float2*)(sm + TVLF_OFF);
    float2* tvlW2 = (float2*)(sm + TVLW_OFF);
    float2* tvgF2 = (float2*)(sm + TVGF_OFF);
    float2* tvgW2 = (float2*)(sm + TVGW_OFF);
    float*  psg   = sm + PSG_OFF;
    float*  psl   = sm + PSL_OFF;
    float*  sgp   = sm + SGP_OFF;
    float*  slp   = sm + SLP_OFF;
    float*  sgv   = sm + SGV_OFF;
    float*  elv   = sm + ELV_OFF;
    float*  isu   = sm + ISU_OFF;
    uint4*  sWcU4 = (uint4*)(sm + WC_OFF);
    float*  sWcg  = sm + WC_OFF;                // overlay: 18432
    float*  sGsA  = sm + WC_OFF + 18432;        // overlay: 8448
    float*  sGsB  = sm + SGSB_OFF;              // 8448
    float*  EgX   = sm + WC_OFF + 26880;        // overlay: 3072
    float*  EgP   = sm + WC_OFF + 18432;        // overlay (after sGsA dead)

    const int b   = blockIdx.x >> 1;
    const unsigned r = ctarank();
    const int tid = threadIdx.x;
    const int w = tid >> 5, lane = tid & 31;
    const ull one2 = 0x3F8000003F800000ULL;

    const unsigned barE1 = s2u(sm + MBAR_OFF);
    const unsigned barE2 = barE1 + 8;
    const unsigned barP  = barE1 + 16;
    if (tid == 0) { mbar_init(barE1, 24); mbar_init(barE2, 288); mbar_init(barP, 512); }
    const unsigned peer = r ^ 1u;
    const unsigned p_ypeer = mapa_u32(s2u(sm + PSL_OFF), peer);
    const unsigned p_sgp   = mapa_u32(s2u(sm + SGP_OFF), peer);
    const unsigned p_slp   = mapa_u32(s2u(sm + SLP_OFF), peer);
    const unsigned p_EgX   = mapa_u32(s2u(sm + WC_OFF + 26880), peer);
    const unsigned p_barE1 = mapa_u32(barE1, peer);
    const unsigned p_barE2 = mapa_u32(barE2, peer);
    const unsigned p_barP  = mapa_u32(barP, peer);
    float2* ypeer = (float2*)(sm + PSL_OFF);

    __syncthreads();
    cluster_sync_all();

    // ---------- El (local conv): packed o-pairs, threads 768..959 ----------
    ull Elpk = 0;
    if (tid >= 768 && tid < 960) {
        int idx = tid - 768;
        int p = idx >> 5, l = idx & 31;
        int o0 = OHALF * r + 2 * p;
        float acc0 = __ldg(&bcl[o0]), acc1 = __ldg(&bcl[o0 + 1]);
        const float* ls = local_states + b * (NI * IL);
        #pragma unroll
        for (int c = 0; c < IL; c++) {
            float sv = __ldg(&ls[c * NI + l]);
            acc0 = fmaf(__ldg(&Wcl[o0 * IL + c]),       sv, acc0);
            acc1 = fmaf(__ldg(&Wcl[(o0 + 1) * IL + c]), sv, acc1);
        }
        Elpk = pk2(__expf(2.f * acc0), __expf(2.f * acc1));
    }

    // preload persistent + precompute data
    for (int i = tid; i < VEC * IL * NI; i += NTHREADS) sWcg[i] = Wcg[i];
    for (int i = tid; i < TT * DIN; i += NTHREADS) {
        int t = i / DIN, k = i - t * DIN;
        sInp[i] = (k < NI) ? __ldg(&local_inputs[(t * BB + b) * NI + k])
                           : __ldg(&global_inputs[(t * BB + b) * NS + (k - NI)]);
    }
    if (tid < NS) sgb[tid] = LAM * __ldg(&distmat[b * NS + tid]);
    for (int i = tid; i < VEC * 128; i += NTHREADS) {
        int d = i >> 7, hh = i & 127;
        sWll[i] = Wll[d * HH + 128 * r + hh];
        sWlg[i] = Wlg[d * HH + 128 * r + hh];
    }
    if (tid < VEC) {
        float wl = -2.f * __ldg(&vl[tid]);
        float wg = -2.f * (1.f - LAM) * __ldg(&vg[tid]);
        tvlW2[tid] = make_float2(wl, wl);
        tvgW2[tid] = make_float2(wg, wg);
    }
    if (tid < JJ) sbias[tid] = g_gbiasC[r * JJ + tid];
    if (tid < 2) isu[tid] = 1.f;
    __syncthreads();

    // xv for t=0 (attn0 raw, per reference)
    if (tid < NI)        xv[tid] = __ldg(&la0[b * NI + tid]) * sInp[tid];
    else if (tid < DIN)  xv[tid] = __ldg(&ga0[b * NS + (tid - NI)]) * sInp[tid];

    // ---------- Eg precompute: ALL 24 o over this rank's 12-c half ----------
    const int og = tid >> 7;
    const int s0 = tid & 127;
    float a00=0.f,a01=0.f,a10=0.f,a11=0.f,a20=0.f,a21=0.f;
    {
        const float* gsb = global_states + (size_t)b * (NS * NI * IL) + (size_t)(12 * r) * (NS * NI);
        for (int i = tid; i < NS * NI; i += NTHREADS) {
            int s = i >> 5, j = i & 31;
            sGsA[s * 33 + j] = gsb[i];
        }
        __syncthreads();
        for (int ci = 0; ci < 12; ci++) {
            float* cur = (ci & 1) ? sGsB : sGsA;
            float* nxt = (ci & 1) ? sGsA : sGsB;
            if (ci < 11) {
                const float* src = gsb + (size_t)(ci + 1) * (NS * NI);
                for (int i = tid; i < NS * NI; i += NTHREADS) {
                    int s = i >> 5, j = i & 31;
                    nxt[s * 33 + j] = src[i];
                }
            }
            int c = 12 * r + ci;
            #pragma unroll 8
            for (int j = 0; j < NI; j++) {
                float gA = cur[s0 * 33 + j];
                float gB = cur[(s0 + 128) * 33 + j];
                float w0 = sWcg[((og*3+0) * IL + c) * NI + j];
                float w1 = sWcg[((og*3+1) * IL + c) * NI + j];
                float w2 = sWcg[((og*3+2) * IL + c) * NI + j];
                a00 = fmaf(w0, gA, a00); a01 = fmaf(w0, gB, a01);
                a10 = fmaf(w1, gA, a10); a11 = fmaf(w1, gB, a11);
                a20 = fmaf(w2, gA, a20); a21 = fmaf(w2, gB, a21);
            }
            __syncthreads();
        }
    }
    {
        int my_lo = 4 * (int)r;
        if (og < my_lo || og >= my_lo + 4) {
            int base = (og - 4 * (int)peer) * 3;
            stc_f32(p_EgX + (unsigned)(((base+0)*NS + s0      ) * 4), a00);
            stc_f32(p_EgX + (unsigned)(((base+0)*NS + s0 + 128) * 4), a01);
            stc_f32(p_EgX + (unsigned)(((base+1)*NS + s0      ) * 4), a10);
            stc_f32(p_EgX + (unsigned)(((base+1)*NS + s0 + 128) * 4), a11);
            stc_f32(p_EgX + (unsigned)(((base+2)*NS + s0      ) * 4), a20);
            stc_f32(p_EgX + (unsigned)(((base+2)*NS + s0 + 128) * 4), a21);
            mbar_arrive_remote(p_barP);
        } else {
            mbar_wait(barP, 0);
            int base = (og - my_lo) * 3;
            float b0 = __ldg(&bcg[og*3+0]);
            float b1 = __ldg(&bcg[og*3+1]);
            float b2 = __ldg(&bcg[og*3+2]);
            EgP[(base+0)*NS + s0      ] = __expf(2.f * (a00 + EgX[(base+0)*NS + s0      ] + b0));
            EgP[(base+0)*NS + s0 + 128] = __expf(2.f * (a01 + EgX[(base+0)*NS + s0 + 128] + b0));
            EgP[(base+1)*NS + s0      ] = __expf(2.f * (a10 + EgX[(base+1)*NS + s0      ] + b1));
            EgP[(base+1)*NS + s0 + 128] = __expf(2.f * (a11 + EgX[(base+1)*NS + s0 + 128] + b1));
            EgP[(base+2)*NS + s0      ] = __expf(2.f * (a20 + EgX[(base+2)*NS + s0      ] + b2));
            EgP[(base+2)*NS + s0 + 128] = __expf(2.f * (a21 + EgX[(base+2)*NS + s0 + 128] + b2));
        }
    }
    __syncthreads();

    const int grp = tid >> 8;
    const int sdx = tid & 255;
    ull Epk0 = 0, Epk1 = 0;
    if (grp < 3) {
        Epk0 = pk2(EgP[(4*grp + 0) * NS + sdx], EgP[(4*grp + 1) * NS + sdx]);
        Epk1 = pk2(EgP[(4*grp + 2) * NS + sdx], EgP[(4*grp + 3) * NS + sdx]);
    }
    __syncthreads();

    {
        const uint4* src = g_W4c + (size_t)r * (KC * JJ);
        for (int i = tid; i < NCACHE * JJ; i += NTHREADS) {
            int slot = i / JJ, jj = i - slot * JJ;
            int kc = (slot < 10) ? slot : (slot + 8);
            sWcU4[i] = src[kc * JJ + jj];
        }
    }
    __syncthreads();

    float bllreg = 0.f, blgreg = 0.f;
    if (lane == 0 && w < VEC) {
        bllreg = __ldg(&bll[w]);
        blgreg = __ldg(&blg[w]);
    }

    float* out_h  = out;
    float* out_c  = out + TT * BB * HH;
    float* out_la = out_c + BB * HH;
    float* out_ga = out_la + TT * BB * NI;

    cluster_sync_all();

    // Barrier roles per step:
    //   bar1 (896):  {w0-23, w28-31} — garr + isu ready
    //   bar2 (768):  w0-23 — cvl ready
    //   bar3 (960):  w0-29 — tv ready
    //   bar4 (960):  w0-29 — partials ready
    //   __syncthreads(): xv/sgv/elv fan-out + cross-step fence
    for (int t = 0; t < TT; t++) {
        const unsigned ph = (unsigned)(t & 1);

        // ---- gates (w0-23, unnormalized xv, split accumulators) ∥ shadow (w30/31) ----
        if (tid < 2 * JJ) {
            int khalf = tid >= JJ;
            int jj = tid - khalf * JJ;
            const uint4* wg = g_W4c + (size_t)r * (KC * JJ) + jj;
            const uint4* ws = sWcU4 + (khalf * 10) * JJ + jj;
            const float4* xv4 = (const float4*)xv;
            float aG0 = 0.f, aG1 = 0.f;
            #pragma unroll
            for (int q = 10; q < 18; q++) {   // gmem chunks first (MLP), all global-k
                int kc = khalf * 18 + q;
                uint4 ww = wg[(size_t)kc * JJ];
                float4 xa = xv4[2 * kc], xb = xv4[2 * kc + 1];
                float2 f0 = __half22float2(*(__half2*)&ww.x);
                float2 f1 = __half22float2(*(__half2*)&ww.y);
                float2 f2 = __half22float2(*(__half2*)&ww.z);
                float2 f3 = __half22float2(*(__half2*)&ww.w);
                aG0 = fmaf(xa.x, f0.x, aG0); aG1 = fmaf(xa.y, f0.y, aG1);
                aG0 = fmaf(xa.z, f1.x, aG0); aG1 = fmaf(xa.w, f1.y, aG1);
                aG0 = fmaf(xb.x, f2.x, aG0); aG1 = fmaf(xb.y, f2.y, aG1);
                aG0 = fmaf(xb.z, f3.x, aG0); aG1 = fmaf(xb.w, f3.y, aG1);
            }
            if (khalf == 0) {
                float aL0 = 0.f, aL1 = 0.f;
                #pragma unroll
                for (int q = 0; q < 4; q++) {   // kc 0-3 = local inputs
                    uint4 ww = ws[q * JJ];
                    float4 xa = xv4[2 * q], xb = xv4[2 * q + 1];
                    float2 f0 = __half22float2(*(__half2*)&ww.x);
                    float2 f1 = __half22float2(*(__half2*)&ww.y);
                    float2 f2 = __half22float2(*(__half2*)&ww.z);
                    float2 f3 = __half22float2(*(__half2*)&ww.w);
                    aL0 = fmaf(xa.x, f0.x, aL0); aL1 = fmaf(xa.y, f0.y, aL1);
                    aL0 = fmaf(xa.z, f1.x, aL0); aL1 = fmaf(xa.w, f1.y, aL1);
                    aL0 = fmaf(xb.x, f2.x, aL0); aL1 = fmaf(xb.y, f2.y, aL1);
                    aL0 = fmaf(xb.z, f3.x, aL0); aL1 = fmaf(xb.w, f3.y, aL1);
                }
                #pragma unroll
                for (int q = 4; q < 10; q++) {  // kc 4-9 global, cached
                    uint4 ww = ws[q * JJ];
                    float4 xa = xv4[2 * q], xb = xv4[2 * q + 1];
                    float2 f0 = __half22float2(*(__half2*)&ww.x);
                    float2 f1 = __half22float2(*(__half2*)&ww.y);
                    float2 f2 = __half22float2(*(__half2*)&ww.z);
                    float2 f3 = __half22float2(*(__half2*)&ww.w);
                    aG0 = fmaf(xa.x, f0.x, aG0); aG1 = fmaf(xa.y, f0.y, aG1);
                    aG0 = fmaf(xa.z, f1.x, aG0); aG1 = fmaf(xa.w, f1.y, aG1);
                    aG0 = fmaf(xb.x, f2.x, aG0); aG1 = fmaf(xb.y, f2.y, aG1);
                    aG0 = fmaf(xb.z, f3.x, aG0); aG1 = fmaf(xb.w, f3.y, aG1);
                }
                garrL[jj]  = aL0 + aL1;
                garrG0[jj] = aG0 + aG1;
            } else {
                #pragma unroll
                for (int q = 0; q < 10; q++) {  // kc 18-27 global, cached
                    int kc = 18 + q;
                    uint4 ww = ws[q * JJ];
                    float4 xa = xv4[2 * kc], xb = xv4[2 * kc + 1];
                    float2 f0 = __half22float2(*(__half2*)&ww.x);
                    float2 f1 = __half22float2(*(__half2*)&ww.y);
                    float2 f2 = __half22float2(*(__half2*)&ww.z);
                    float2 f3 = __half22float2(*(__half2*)&ww.w);
                    aG0 = fmaf(xa.x, f0.x, aG0); aG1 = fmaf(xa.y, f0.y, aG1);
                    aG0 = fmaf(xa.z, f1.x, aG0); aG1 = fmaf(xa.w, f1.y, aG1);
                    aG0 = fmaf(xb.x, f2.x, aG0); aG1 = fmaf(xb.y, f2.y, aG1);
                    aG0 = fmaf(xb.z, f3.x, aG0); aG1 = fmaf(xb.w, f3.y, aG1);
                }
                garrG1[jj] = aG0 + aG1;
            }
        } else if (w == 30) {
            if (t > 0) {
                float ev[8]; float s = 0.f;
                #pragma unroll
                for (int i = 0; i < 8; i++) { ev[i] = sgv[lane + 32 * i]; s += ev[i]; }
                #pragma unroll
                for (int off = 16; off; off >>= 1) s += __shfl_xor_sync(0xffffffffu, s, off);
                float ig2 = frcp(s);
                if (lane == 0) isu[1] = ig2;
                if (r == 0) {
                    float* og_ = out_ga + (size_t)((t - 1) * BB + b) * NS;
                    #pragma unroll
                    for (int i = 0; i < 8; i++) og_[lane + 32 * i] = ev[i] * ig2;
                }
            }
        } else if (w == 31) {
            if (t > 0) {
                float e = elv[lane];
                float s = e;
                #pragma unroll
                for (int off = 16; off; off >>= 1) s += __shfl_xor_sync(0xffffffffu, s, off);
                float il2 = frcp(s);
                if (lane == 0) isu[0] = il2;
                if (r == 1) out_la[(size_t)((t - 1) * BB + b) * NI + lane] = e * il2;
            }
        }
        if (w < 24 || w >= 28) NBAR(1, 896);

        // ---- LSTM (w0-3) + out_h (w28-31) ----
        if (tid < 128) {
            float isl = isu[0], isg = isu[1];
            float gi = fmaf(garrL[tid], isl,
                       fmaf(garrG0[tid] + garrG1[tid], isg, sbias[tid]));
            float gg = fmaf(garrL[128 + tid], isl,
                       fmaf(garrG0[128 + tid] + garrG1[128 + tid], isg, sbias[128 + tid]));
            float si = frcp(1.f + __expf(-gi));
            float tg = fmaf(-2.f, frcp(1.f + __expf(2.f * gg)), 1.f);
            cvl[tid] = si * tg;
        } else if (tid >= 896) {
            int hid = tid - 896;
            float isl = isu[0], isg = isu[1];
            float gi = fmaf(garrL[hid], isl,
                       fmaf(garrG0[hid] + garrG1[hid], isg, sbias[hid]));
            float gg = fmaf(garrL[128 + hid], isl,
                       fmaf(garrG0[128 + hid] + garrG1[128 + hid], isg, sbias[128 + hid]));
            float go = fmaf(garrL[256 + hid], isl,
                       fmaf(garrG0[256 + hid] + garrG1[256 + hid], isg, sbias[256 + hid]));
            float si = frcp(1.f + __expf(-gi));
            float tg = fmaf(-2.f, frcp(1.f + __expf(2.f * gg)), 1.f);
            float cval = si * tg;
            float so = frcp(1.f + __expf(-go));
            float tc = fmaf(-2.f, frcp(1.f + __expf(2.f * cval)), 1.f);
            int hg = 128 * r + hid;
            out_h[(size_t)(t * BB + b) * HH + hg] = so * tc;
            if (t == TT - 1) out_c[(size_t)b * HH + hg] = cval;
        }
        if (w < 24) NBAR(2, 768);

        // ---- y dots (c-half) + E1 exchange + tv ----
        if (w < VEC) {
            float a = 0.f, bg = 0.f;
            const float* wr  = sWll + w * 128;
            const float* wr2 = sWlg + w * 128;
            #pragma unroll
            for (int i = 0; i < 4; i++) {
                float cc = cvl[lane + 32 * i];
                a  = fmaf(cc, wr[lane + 32 * i], a);
                bg = fmaf(cc, wr2[lane + 32 * i], bg);
            }
            #pragma unroll
            for (int off = 16; off; off >>= 1) {
                a  += __shfl_xor_sync(0xffffffffu, a, off);
                bg += __shfl_xor_sync(0xffffffffu, bg, off);
            }
            if (lane == 0) {
                stc_b64(p_ypeer + (unsigned)(w * 8), a, bg);
                mbar_arrive_remote(p_barE1);
                mbar_wait(barE1, ph);
                float2 p = ypeer[w];
                float Fl = __expf(2.f * (a  + p.x + bllreg));
                float Fg = __expf(2.f * (bg + p.y + blgreg));
                tvlF2[w] = make_float2(Fl, Fl);
                tvgF2[w] = make_float2(Fg, Fg);
            }
        }
        if (w < 30) NBAR(3, 960);

        // ---- partials: packed f32x2 ----
        if (grp < 3) {
            const ull* tF = (const ull*)tvgF2;
            const ull* tW = (const ull*)tvgW2;
            ull acc0 = 0, acc1 = 0;
            #pragma unroll
            for (int dq = 0; dq < 6; dq++) {
                ull F1 = tF[4*dq+0], W1 = tW[4*dq+0];
                ull F2 = tF[4*dq+1], W2 = tW[4*dq+1];
                ull F3 = tF[4*dq+2], W3 = tW[4*dq+2];
                ull F4 = tF[4*dq+3], W4 = tW[4*dq+3];
                {
                    ull D1 = fma2(Epk0, F1, one2), D2 = fma2(Epk0, F2, one2);
                    ull D3 = fma2(Epk0, F3, one2), D4 = fma2(Epk0, F4, one2);
                    ull p12 = mul2(D1, D2), p34 = mul2(D3, D4);
                    ull n12 = fma2(W2, D1, mul2(W1, D2));
                    ull n34 = fma2(W4, D3, mul2(W3, D4));
                    ull num = fma2(n34, p12, mul2(n12, p34));
                    acc0 = fma2(num, rcp2(mul2(p12, p34)), acc0);
                }
                {
                    ull D1 = fma2(Epk1, F1, one2), D2 = fma2(Epk1, F2, one2);
                    ull D3 = fma2(Epk1, F3, one2), D4 = fma2(Epk1, F4, one2);
                    ull p12 = mul2(D1, D2), p34 = mul2(D3, D4);
                    ull n12 = fma2(W2, D1, mul2(W1, D2));
                    ull n34 = fma2(W4, D3, mul2(W3, D4));
                    ull num = fma2(n34, p12, mul2(n12, p34));
                    acc1 = fma2(num, rcp2(mul2(p12, p34)), acc1);
                }
            }
            float2 u0 = upk(acc0), u1 = upk(acc1);
            psg[grp * NS + sdx] = (u0.x + u0.y) + (u1.x + u1.y);
        } else if (tid < 960) {
            int idx = tid - 768;
            const ull* tF = (const ull*)tvlF2;
            const ull* tW = (const ull*)tvlW2;
            ull acc = 0;
            #pragma unroll
            for (int dq = 0; dq < 6; dq++) {
                ull F1 = tF[4*dq+0], W1 = tW[4*dq+0];
                ull F2 = tF[4*dq+1], W2 = tW[4*dq+1];
                ull F3 = tF[4*dq+2], W3 = tW[4*dq+2];
                ull F4 = tF[4*dq+3], W4 = tW[4*dq+3];
                ull D1 = fma2(Elpk, F1, one2), D2 = fma2(Elpk, F2, one2);
                ull D3 = fma2(Elpk, F3, one2), D4 = fma2(Elpk, F4, one2);
                ull p12 = mul2(D1, D2), p34 = mul2(D3, D4);
                ull n12 = fma2(W2, D1, mul2(W1, D2));
                ull n34 = fma2(W4, D3, mul2(W3, D4));
                ull num = fma2(n34, p12, mul2(n12, p34));
                acc = fma2(num, rcp2(mul2(p12, p34)), acc);
            }
            float2 u = upk(acc);
            psl[idx] = u.x + u.y;
        }
        if (w < 30) NBAR(4, 960);

        // ---- reduce + E2 exchange + raw exp + xv(t+1) ----
        if (tid < NS) {
            float myg = psg[tid] + psg[NS + tid] + psg[2 * NS + tid];
            float base = myg + sgb[tid];          // hide FADD in pre-wait slot
            stc_f32(p_sgp + (unsigned)(tid * 4), myg);
            mbar_arrive_remote(p_barE2);
            mbar_wait(barE2, ph);
            float e = __expf(base + sgp[tid]);
            sgv[tid] = e;
            if (t + 1 < TT) xv[NI + tid] = e * sInp[(t + 1) * DIN + NI + tid];
        } else if (tid < NS + NI) {
            int l = tid - NS;
            float myl = 0.f;
            #pragma unroll
            for (int p = 0; p < 6; p++) myl += psl[p * NI + l];
            stc_f32(p_slp + (unsigned)(l * 4), myl);
            mbar_arrive_remote(p_barE2);
            mbar_wait(barE2, ph);
            float e = __expf(myl + slp[l]);
            elv[l] = e;
            if (t + 1 < TT) xv[l] = e * sInp[(t + 1) * DIN + l];
        }
        __syncthreads();
    }

    // epilogue: outputs for t = TT-1
    if (w == 30) {
        float ev[8]; float s = 0.f;
        #pragma unroll
        for (int i = 0; i < 8; i++) { ev[i] = sgv[lane + 32 * i]; s += ev[i]; }
        #pragma unroll
        for (int off = 16; off; off >>= 1) s += __shfl_xor_sync(0xffffffffu, s, off);
        float ig2 = frcp(s);
        if (r == 0) {
            float* og_ = out_ga + (size_t)((TT - 1) * BB + b) * NS;
            #pragma unroll
            for (int i = 0; i < 8; i++) og_[lane + 32 * i] = ev[i] * ig2;
        }
    } else if (w == 31) {
        float e = elv[lane];
        float s = e;
        #pragma unroll
        for (int off = 16; off; off >>= 1) s += __shfl_xor_sync(0xffffffffu, s, off);
        float il2 = frcp(s);
        if (r == 1) out_la[(size_t)((TT - 1) * BB + b) * NI + lane] = e * il2;
    }

    cluster_sync_all();
}

extern "C" void kernel_launch(void* const* d_in, const int* in_sizes, int n_in,
                              void* d_out, int out_size) {
    const float* local_inputs  = (const float*)d_in[0];
    const float* global_inputs = (const float*)d_in[1];
    const float* local_states  = (const float*)d_in[2];
    const float* global_states = (const float*)d_in[3];
    const float* distmat       = (const float*)d_in[4];
    const float* la0           = (const float*)d_in[5];
    const float* ga0           = (const float*)d_in[6];
    const float* Wcl = (const float*)d_in[7];
    const float* bcl = (const float*)d_in[8];
    const float* Wll = (const float*)d_in[9];
    const float* bll = (const float*)d_in[10];
    const float* vl  = (const float*)d_in[11];
    const float* Wcg = (const float*)d_in[12];
    const float* bcg = (const float*)d_in[13];
    const float* Wlg = (const float*)d_in[14];
    const float* blg = (const float*)d_in[15];
    const float* vg  = (const float*)d_in[16];
    const float* Wih = (const float*)d_in[17];
    const float* bih = (const float*)d_in[18];
    const float* bhh = (const float*)d_in[19];
    float* out = (float*)d_out;

    cudaFuncSetAttribute(spatial_attn_kernel,
                         cudaFuncAttributeMaxDynamicSharedMemorySize, SMEM_BYTES);

    prep_kernel<<<(2 * KC * JJ + 255) / 256, 256>>>(Wih, bih, bhh);
    spatial_attn_kernel<<<2 * BB, NTHREADS, SMEM_BYTES>>>(
        local_inputs, global_inputs, local_states, global_states, distmat,
        la0, ga0, Wcl, bcl, Wll, bll, vl, Wcg, bcg, Wlg, blg, vg, out);
}